// round 8
// baseline (speedup 1.0000x reference)
#include <cuda_runtime.h>
#include <cuda_fp16.h>
#include <cstdint>

// ---------------------------------------------------------------------------
// Problem constants
// ---------------------------------------------------------------------------
#define B_ 4
#define T_ 160
#define U_ 80
#define DE 640
#define HH 640
#define VV 1024
#define TU (T_ * U_)          // 12800
#define MTOT (B_ * TU)        // 51200

// Joint GEMM tiling
#define BM 128
#define BN 128
#define BK 64
#define KITERS (HH / BK)      // 10
#define STAGES 3

// ---------------------------------------------------------------------------
// Device scratch
// ---------------------------------------------------------------------------
__device__ float g_proj_e[B_ * T_ * HH];
__device__ float g_proj_d[B_ * U_ * HH];
__device__ __align__(16) __half g_A[(size_t)MTOT * HH];   // fp16(tanh(...))
__device__ __align__(16) __half g_B[VV * HH];             // W2^T fp16, [n][k]

// ---------------------------------------------------------------------------
// Helpers
// ---------------------------------------------------------------------------
__device__ __forceinline__ uint32_t smem_u32(const void* p) {
    uint32_t a;
    asm("{ .reg .u64 t; cvta.to.shared.u64 t, %1; cvt.u32.u64 %0, t; }"
        : "=r"(a) : "l"(p));
    return a;
}

__device__ __forceinline__ float fast_tanh(float x) {
    float e;
    asm("ex2.approx.f32 %0, %1;" : "=f"(e) : "f"(x * 2.885390081777927f));
    float r;
    asm("rcp.approx.f32 %0, %1;" : "=f"(r) : "f"(e + 1.0f));
    return fmaf(-2.0f, r, 1.0f);
}

#define CP_ASYNC16(saddr, gptr) \
    asm volatile("cp.async.cg.shared.global [%0], [%1], 16;" \
                 :: "r"(saddr), "l"(gptr))
#define CP_COMMIT()  asm volatile("cp.async.commit_group;" ::: "memory")
#define CP_WAIT1()   asm volatile("cp.async.wait_group 1;" ::: "memory")
#define CP_WAIT0()   asm volatile("cp.async.wait_group 0;" ::: "memory")

#define LDSM4(r0, r1, r2, r3, a) \
    asm volatile("ldmatrix.sync.aligned.m8n8.x4.shared.b16 {%0,%1,%2,%3}, [%4];" \
                 : "=r"(r0), "=r"(r1), "=r"(r2), "=r"(r3) : "r"(a))

// fp16-accumulator HMMA: D(f16x2 x2) = A(f16) * B(f16) + D
#define MMA16816F16(d, a, b0, b1) \
    asm volatile("mma.sync.aligned.m16n8k16.row.col.f16.f16.f16.f16 " \
                 "{%0,%1}, {%2,%3,%4,%5}, {%6,%7}, {%0,%1};" \
                 : "+r"((d)[0]), "+r"((d)[1]) \
                 : "r"((a)[0]), "r"((a)[1]), "r"((a)[2]), "r"((a)[3]), \
                   "r"(b0), "r"(b1))

// ---------------------------------------------------------------------------
// Stage 1: both projections. BM=64, BN=32, BK=16, 128 threads. (unchanged)
// ---------------------------------------------------------------------------
__global__ void __launch_bounds__(128)
proj_both(const float* __restrict__ enc,
          const float* __restrict__ dec,
          const float* __restrict__ W1,
          const float* __restrict__ b1,
          float* __restrict__ pe,
          float* __restrict__ pd)
{
    __shared__ float As[16][65];
    __shared__ float Bs[16][32];

    const int ltid = threadIdx.x;
    const bool is_dec = (blockIdx.y >= 10);
    const int m0 = (is_dec ? (blockIdx.y - 10) : blockIdx.y) * 64;
    const int n0 = blockIdx.x * 32;

    const float* __restrict__ A    = is_dec ? dec : enc;
    const float* __restrict__ W    = is_dec ? (W1 + (size_t)DE * HH) : W1;
    const float* __restrict__ bias = is_dec ? b1 : nullptr;
    float* __restrict__ C          = is_dec ? pd : pe;

    const int bk  = ltid >> 3;
    const int bn  = (ltid & 7) * 4;
    const int tx  = ltid & 7;
    const int ty  = ltid >> 3;

    float acc[4][4] = {};

    float4 av[2], bv;
    #pragma unroll
    for (int i = 0; i < 2; i++) {
        int ci = ltid + i * 128;
        av[i] = *(const float4*)&A[(size_t)(m0 + (ci >> 2)) * DE + (ci & 3) * 4];
    }
    bv = *(const float4*)&W[(size_t)bk * HH + n0 + bn];

    for (int k0 = 0; k0 < DE; k0 += 16) {
        #pragma unroll
        for (int i = 0; i < 2; i++) {
            int ci = ltid + i * 128;
            int arow = ci >> 2;
            int ak4  = (ci & 3) * 4;
            As[ak4 + 0][arow] = av[i].x;
            As[ak4 + 1][arow] = av[i].y;
            As[ak4 + 2][arow] = av[i].z;
            As[ak4 + 3][arow] = av[i].w;
        }
        *(float4*)&Bs[bk][bn] = bv;
        __syncthreads();

        if (k0 + 16 < DE) {
            #pragma unroll
            for (int i = 0; i < 2; i++) {
                int ci = ltid + i * 128;
                av[i] = *(const float4*)&A[(size_t)(m0 + (ci >> 2)) * DE +
                                           k0 + 16 + (ci & 3) * 4];
            }
            bv = *(const float4*)&W[(size_t)(k0 + 16 + bk) * HH + n0 + bn];
        }

        #pragma unroll
        for (int k = 0; k < 16; k++) {
            float a[4], b[4];
            #pragma unroll
            for (int j = 0; j < 4; j++) a[j] = As[k][ty * 4 + j];
            #pragma unroll
            for (int i = 0; i < 4; i++) b[i] = Bs[k][tx * 4 + i];
            #pragma unroll
            for (int j = 0; j < 4; j++)
                #pragma unroll
                for (int i = 0; i < 4; i++)
                    acc[j][i] = fmaf(a[j], b[i], acc[j][i]);
        }
        __syncthreads();
    }

    #pragma unroll
    for (int j = 0; j < 4; j++) {
        const int row = m0 + ty * 4 + j;
        #pragma unroll
        for (int i = 0; i < 4; i++) {
            float v = acc[j][i];
            if (bias) v += bias[n0 + tx * 4 + i];
            C[(size_t)row * HH + n0 + tx * 4 + i] = v;
        }
    }
}

// ---------------------------------------------------------------------------
// Stage 1.5a: W2 transpose -> fp16, tiled through smem (unchanged)
// ---------------------------------------------------------------------------
__global__ void prep_w2(const float* __restrict__ W2, __half* __restrict__ B)
{
    __shared__ float tile[32][33];
    const int n0 = blockIdx.x * 32;
    const int k0 = blockIdx.y * 32;
    const int x = threadIdx.x & 31;
    const int y = threadIdx.x >> 5;

    #pragma unroll
    for (int j = 0; j < 4; j++)
        tile[y + j * 8][x] = W2[(size_t)(k0 + y + j * 8) * VV + n0 + x];
    __syncthreads();

    #pragma unroll
    for (int j = 0; j < 4; j++) {
        int ny = y + j * 8;
        B[(size_t)(n0 + ny) * HH + k0 + x] = __float2half_rn(tile[x][ny]);
    }
}

// ---------------------------------------------------------------------------
// Stage 1.5b: A = fp16(tanh(pe + pd)); grid (U, T, B), no div/mod (unchanged)
// ---------------------------------------------------------------------------
__global__ void __launch_bounds__(160)
prep_a(__half* __restrict__ A)
{
    const int u = blockIdx.x;
    const int t = blockIdx.y;
    const int b = blockIdx.z;
    const int q4 = threadIdx.x * 4;

    const float4 e = *(const float4*)&g_proj_e[(size_t)(b * T_ + t) * HH + q4];
    const float4 d = *(const float4*)&g_proj_d[(size_t)(b * U_ + u) * HH + q4];

    __half h[4];
    h[0] = __float2half_rn(fast_tanh(e.x + d.x));
    h[1] = __float2half_rn(fast_tanh(e.y + d.y));
    h[2] = __float2half_rn(fast_tanh(e.z + d.z));
    h[3] = __float2half_rn(fast_tanh(e.w + d.w));

    const size_t row = (size_t)b * TU + t * U_ + u;
    *(uint2*)&A[row * HH + q4] = *(uint2*)h;
}

// ---------------------------------------------------------------------------
// Stage 2: HMMA joint GEMM with fp16 accumulators + windowed fp32 promotion.
// BM=128, BN=128, BK=64; 128 threads = 4 warps (2M x 2N), warp tile 64x64.
// fp16 acc over 2-iter windows (K=128), promoted to fp32 masters 5x.
// 3-stage cp.async pipeline, one sync/iter, 2 CTAs/SM.
// ---------------------------------------------------------------------------
#define STG_STRIDE 32768u
#define SMEM_TOTAL (STAGES * 32768)

__device__ __forceinline__ void load_buf(uint32_t sbuf,
                                         const __half* __restrict__ A,
                                         const __half* __restrict__ B,
                                         int m0, int n0, int k0)
{
    const int tid = threadIdx.x;
    #pragma unroll
    for (int i = 0; i < 8; i++) {
        int ci = tid + i * 128;
        int row = ci >> 3;
        int ck = ci & 7;
        uint32_t so = sbuf + row * 128 + ((ck ^ (row & 7)) << 4);
        CP_ASYNC16(so, A + (size_t)(m0 + row) * HH + k0 + ck * 8);
    }
    #pragma unroll
    for (int i = 0; i < 8; i++) {
        int ci = tid + i * 128;
        int row = ci >> 3;
        int ck = ci & 7;
        uint32_t so = sbuf + 16384u + row * 128 + ((ck ^ (row & 7)) << 4);
        CP_ASYNC16(so, B + (size_t)(n0 + row) * HH + k0 + ck * 8);
    }
}

__global__ void __launch_bounds__(128, 2)
joint_gemm(const __half* __restrict__ A,
           const __half* __restrict__ B,
           const float* __restrict__ b2,
           float* __restrict__ out)
{
    extern __shared__ __align__(1024) char smem[];
    const uint32_t sb = smem_u32(smem);

    const int tid  = threadIdx.x;
    const int lane = tid & 31;
    const int wid  = tid >> 5;
    const int wm   = wid & 1;
    const int wn   = wid >> 1;
    const int n0   = blockIdx.x * BN;
    const int m0   = blockIdx.y * BM;

    const int lml = lane & 15;
    const int lmh = lane >> 4;

    float acc32[4][8][4];           // fp32 masters (cold: touched 5x)
    #pragma unroll
    for (int a = 0; a < 4; a++)
        #pragma unroll
        for (int n = 0; n < 8; n++)
            #pragma unroll
            for (int i = 0; i < 4; i++) acc32[a][n][i] = 0.0f;

    uint32_t acc16[4][8][2];        // fp16x2 window accumulators (hot)

    load_buf(sb,              A, B, m0, n0, 0);
    CP_COMMIT();
    load_buf(sb + STG_STRIDE, A, B, m0, n0, BK);
    CP_COMMIT();
    CP_WAIT1();
    __syncthreads();

    for (int c = 0; c < KITERS; c++) {
        const uint32_t sbuf = sb + (uint32_t)(c % STAGES) * STG_STRIDE;

        if (c + 2 < KITERS) {
            load_buf(sb + (uint32_t)((c + 2) % STAGES) * STG_STRIDE,
                     A, B, m0, n0, (c + 2) * BK);
            CP_COMMIT();
        }

        if ((c & 1) == 0) {         // window start: zero fp16 accumulators
            #pragma unroll
            for (int a = 0; a < 4; a++)
                #pragma unroll
                for (int n = 0; n < 8; n++) {
                    acc16[a][n][0] = 0u;
                    acc16[a][n][1] = 0u;
                }
        }

        #pragma unroll
        for (int ks = 0; ks < 4; ks++) {
            const int ck = 2 * ks + lmh;

            uint32_t af[4][4];
            #pragma unroll
            for (int a = 0; a < 4; a++) {
                uint32_t row = (uint32_t)(wm * 64 + a * 16 + lml);
                LDSM4(af[a][0], af[a][1], af[a][2], af[a][3],
                      sbuf + row * 128 + (uint32_t)((ck ^ (row & 7)) << 4));
            }
            uint32_t bf[4][4];
            #pragma unroll
            for (int p = 0; p < 4; p++) {
                uint32_t row = (uint32_t)(wn * 64 + p * 16 + lml);
                LDSM4(bf[p][0], bf[p][1], bf[p][2], bf[p][3],
                      sbuf + 16384u + row * 128 +
                      (uint32_t)((ck ^ (row & 7)) << 4));
            }
            #pragma unroll
            for (int a = 0; a < 4; a++)
                #pragma unroll
                for (int n = 0; n < 8; n++) {
                    int p = n >> 1, s = n & 1;
                    MMA16816F16(acc16[a][n], af[a], bf[p][s], bf[p][s + 2]);
                }
        }

        if ((c & 1) == 1) {         // window end: promote fp16 -> fp32 masters
            #pragma unroll
            for (int a = 0; a < 4; a++)
                #pragma unroll
                for (int n = 0; n < 8; n++) {
                    float2 f0 = __half22float2(
                        *reinterpret_cast<__half2*>(&acc16[a][n][0]));
                    float2 f1 = __half22float2(
                        *reinterpret_cast<__half2*>(&acc16[a][n][1]));
                    acc32[a][n][0] += f0.x;
                    acc32[a][n][1] += f0.y;
                    acc32[a][n][2] += f1.x;
                    acc32[a][n][3] += f1.y;
                }
        }

        if (c + 2 < KITERS) CP_WAIT1();
        else                CP_WAIT0();
        __syncthreads();
    }

    // epilogue: +b2, direct stores
    #pragma unroll
    for (int n = 0; n < 8; n++) {
        const int col = n0 + wn * 64 + n * 8 + (lane & 3) * 2;
        const float2 bb = *(const float2*)&b2[col];
        #pragma unroll
        for (int a = 0; a < 4; a++) {
            const size_t r0 = (size_t)m0 + wm * 64 + a * 16 + (lane >> 2);
            float2 o0 = { acc32[a][n][0] + bb.x, acc32[a][n][1] + bb.y };
            float2 o1 = { acc32[a][n][2] + bb.x, acc32[a][n][3] + bb.y };
            *(float2*)&out[r0 * VV + col]       = o0;
            *(float2*)&out[(r0 + 8) * VV + col] = o1;
        }
    }
}

// ---------------------------------------------------------------------------
// Launch
// ---------------------------------------------------------------------------
extern "C" void kernel_launch(void* const* d_in, const int* in_sizes, int n_in,
                              void* d_out, int out_size)
{
    const float* enc = (const float*)d_in[0];
    const float* dec = (const float*)d_in[1];
    const float* W1  = (const float*)d_in[2];
    const float* b1  = (const float*)d_in[3];
    const float* W2  = (const float*)d_in[4];
    const float* b2  = (const float*)d_in[5];
    float* out = (float*)d_out;

    float *pe = nullptr, *pd = nullptr;
    __half *ga = nullptr, *gb = nullptr;
    cudaGetSymbolAddress((void**)&pe, g_proj_e);
    cudaGetSymbolAddress((void**)&pd, g_proj_d);
    cudaGetSymbolAddress((void**)&ga, g_A);
    cudaGetSymbolAddress((void**)&gb, g_B);

    cudaFuncSetAttribute(joint_gemm,
                         cudaFuncAttributeMaxDynamicSharedMemorySize, SMEM_TOTAL);

    proj_both<<<dim3(HH / 32, 15), 128>>>(enc, dec, W1, b1, pe, pd);
    prep_w2<<<dim3(VV / 32, HH / 32), 256>>>(W2, gb);
    prep_a<<<dim3(U_, T_, B_), 160>>>(ga);

    joint_gemm<<<dim3(VV / BN, MTOT / BM), 128, SMEM_TOTAL>>>(ga, gb, b2, out);
}

// round 9
// speedup vs baseline: 1.1035x; 1.1035x over previous
#include <cuda_runtime.h>
#include <cuda_fp16.h>
#include <cstdint>

// ---------------------------------------------------------------------------
// Problem constants
// ---------------------------------------------------------------------------
#define B_ 4
#define T_ 160
#define U_ 80
#define DE 640
#define HH 640
#define VV 1024
#define TU (T_ * U_)          // 12800
#define MTOT (B_ * TU)        // 51200

// Joint GEMM tiling
#define BM 128
#define BN 128
#define BK 64
#define KITERS (HH / BK)      // 10
#define STAGES 3

// ---------------------------------------------------------------------------
// Device scratch
// ---------------------------------------------------------------------------
__device__ float g_proj_e[B_ * T_ * HH];
__device__ float g_proj_d[B_ * U_ * HH];
__device__ __align__(16) __half g_A[(size_t)MTOT * HH];   // fp16(tanh(...))
__device__ __align__(16) __half g_B[VV * HH];             // W2^T fp16, [n][k]

// ---------------------------------------------------------------------------
// Helpers
// ---------------------------------------------------------------------------
__device__ __forceinline__ uint32_t smem_u32(const void* p) {
    uint32_t a;
    asm("{ .reg .u64 t; cvta.to.shared.u64 t, %1; cvt.u32.u64 %0, t; }"
        : "=r"(a) : "l"(p));
    return a;
}

__device__ __forceinline__ float fast_tanh(float x) {
    float e;
    asm("ex2.approx.f32 %0, %1;" : "=f"(e) : "f"(x * 2.885390081777927f));
    float r;
    asm("rcp.approx.f32 %0, %1;" : "=f"(r) : "f"(e + 1.0f));
    return fmaf(-2.0f, r, 1.0f);
}

#define CP_ASYNC16(saddr, gptr) \
    asm volatile("cp.async.cg.shared.global [%0], [%1], 16;" \
                 :: "r"(saddr), "l"(gptr))
#define CP_COMMIT()  asm volatile("cp.async.commit_group;" ::: "memory")
#define CP_WAIT1()   asm volatile("cp.async.wait_group 1;" ::: "memory")
#define CP_WAIT0()   asm volatile("cp.async.wait_group 0;" ::: "memory")

#define LDSM4(r0, r1, r2, r3, a) \
    asm volatile("ldmatrix.sync.aligned.m8n8.x4.shared.b16 {%0,%1,%2,%3}, [%4];" \
                 : "=r"(r0), "=r"(r1), "=r"(r2), "=r"(r3) : "r"(a))

#define MMA16816(d, a, b0, b1) \
    asm volatile("mma.sync.aligned.m16n8k16.row.col.f32.f16.f16.f32 " \
                 "{%0,%1,%2,%3}, {%4,%5,%6,%7}, {%8,%9}, {%0,%1,%2,%3};" \
                 : "+f"((d)[0]), "+f"((d)[1]), "+f"((d)[2]), "+f"((d)[3]) \
                 : "r"((a)[0]), "r"((a)[1]), "r"((a)[2]), "r"((a)[3]), \
                   "r"(b0), "r"(b1))

// ---------------------------------------------------------------------------
// Stage 1 (fused): projections + W2 transpose in ONE launch, 128 threads.
// grid = (20, 47):
//   y 0..9   : enc projection, m-tile = y        (BM=64, BN=32, BK=16)
//   y 10..14 : dec projection, m-tile = y-10
//   y 15..46 : W2 transpose tile, n0 = (y-15)*32, k0 = x*32
// ---------------------------------------------------------------------------
__global__ void __launch_bounds__(128)
proj_and_w2(const float* __restrict__ enc,
            const float* __restrict__ dec,
            const float* __restrict__ W1,
            const float* __restrict__ b1,
            const float* __restrict__ W2,
            float* __restrict__ pe,
            float* __restrict__ pd,
            __half* __restrict__ Bt)
{
    const int ltid = threadIdx.x;

    if (blockIdx.y >= 15) {
        // ---- W2 transpose tile: Bt[n][k] = fp16(W2[k][n]) ----
        __shared__ float tile[32][33];
        const int n0 = (blockIdx.y - 15) * 32;
        const int k0 = blockIdx.x * 32;
        const int x = ltid & 31;
        const int y = ltid >> 5;          // 0..3

        #pragma unroll
        for (int j = 0; j < 8; j++)
            tile[y + j * 4][x] = W2[(size_t)(k0 + y + j * 4) * VV + n0 + x];
        __syncthreads();

        #pragma unroll
        for (int j = 0; j < 8; j++) {
            int ny = y + j * 4;
            Bt[(size_t)(n0 + ny) * HH + k0 + x] = __float2half_rn(tile[x][ny]);
        }
        return;
    }

    // ---- projection path ----
    __shared__ float As[16][65];
    __shared__ float Bs[16][32];

    const bool is_dec = (blockIdx.y >= 10);
    const int m0 = (is_dec ? (blockIdx.y - 10) : blockIdx.y) * 64;
    const int n0 = blockIdx.x * 32;

    const float* __restrict__ A    = is_dec ? dec : enc;
    const float* __restrict__ W    = is_dec ? (W1 + (size_t)DE * HH) : W1;
    const float* __restrict__ bias = is_dec ? b1 : nullptr;
    float* __restrict__ C          = is_dec ? pd : pe;

    const int bk  = ltid >> 3;
    const int bn  = (ltid & 7) * 4;
    const int tx  = ltid & 7;
    const int ty  = ltid >> 3;

    float acc[4][4] = {};

    float4 av[2], bv;
    #pragma unroll
    for (int i = 0; i < 2; i++) {
        int ci = ltid + i * 128;
        av[i] = *(const float4*)&A[(size_t)(m0 + (ci >> 2)) * DE + (ci & 3) * 4];
    }
    bv = *(const float4*)&W[(size_t)bk * HH + n0 + bn];

    for (int k0 = 0; k0 < DE; k0 += 16) {
        #pragma unroll
        for (int i = 0; i < 2; i++) {
            int ci = ltid + i * 128;
            int arow = ci >> 2;
            int ak4  = (ci & 3) * 4;
            As[ak4 + 0][arow] = av[i].x;
            As[ak4 + 1][arow] = av[i].y;
            As[ak4 + 2][arow] = av[i].z;
            As[ak4 + 3][arow] = av[i].w;
        }
        *(float4*)&Bs[bk][bn] = bv;
        __syncthreads();

        if (k0 + 16 < DE) {
            #pragma unroll
            for (int i = 0; i < 2; i++) {
                int ci = ltid + i * 128;
                av[i] = *(const float4*)&A[(size_t)(m0 + (ci >> 2)) * DE +
                                           k0 + 16 + (ci & 3) * 4];
            }
            bv = *(const float4*)&W[(size_t)(k0 + 16 + bk) * HH + n0 + bn];
        }

        #pragma unroll
        for (int k = 0; k < 16; k++) {
            float a[4], b[4];
            #pragma unroll
            for (int j = 0; j < 4; j++) a[j] = As[k][ty * 4 + j];
            #pragma unroll
            for (int i = 0; i < 4; i++) b[i] = Bs[k][tx * 4 + i];
            #pragma unroll
            for (int j = 0; j < 4; j++)
                #pragma unroll
                for (int i = 0; i < 4; i++)
                    acc[j][i] = fmaf(a[j], b[i], acc[j][i]);
        }
        __syncthreads();
    }

    #pragma unroll
    for (int j = 0; j < 4; j++) {
        const int row = m0 + ty * 4 + j;
        #pragma unroll
        for (int i = 0; i < 4; i++) {
            float v = acc[j][i];
            if (bias) v += bias[n0 + tx * 4 + i];
            C[(size_t)row * HH + n0 + tx * 4 + i] = v;
        }
    }
}

// ---------------------------------------------------------------------------
// Stage 1.5: tiled A-prep. A = fp16(tanh(pe + pd)).
// grid (U/16, T/16, B*5): z = b*5 + hs; tile = 16t x 16u x 128h.
// smem traffic replaces the 262MB of repeated L2 reads with 16MB.
// Stores: 16 lanes x uint4 = 256B contiguous per (t,u) row.
// ---------------------------------------------------------------------------
__global__ void __launch_bounds__(256)
prep_a(__half* __restrict__ A)
{
    __shared__ float4 pe4[16][33];   // 16 t-rows x 128 h (32 float4, pad 33)
    __shared__ float4 pd4[16][33];   // 16 u-rows x 128 h

    const int u0 = blockIdx.x * 16;
    const int t0 = blockIdx.y * 16;
    const int b  = blockIdx.z / 5;
    const int h0 = (blockIdx.z - b * 5) * 128;

    const int tid = threadIdx.x;

    // load: 16 rows x 32 float4 each = 512 float4 per tensor, 2 per thread
    {
        const int r  = tid >> 4;          // 0..15
        const int c4 = tid & 15;          // 0..15 (+16 on second pass)
        const float4* pe_g = (const float4*)&g_proj_e[(size_t)(b * T_ + t0 + r) * HH + h0];
        const float4* pd_g = (const float4*)&g_proj_d[(size_t)(b * U_ + u0 + r) * HH + h0];
        pe4[r][c4]      = pe_g[c4];
        pe4[r][c4 + 16] = pe_g[c4 + 16];
        pd4[r][c4]      = pd_g[c4];
        pd4[r][c4 + 16] = pd_g[c4 + 16];
    }
    __syncthreads();

    // compute: thread owns (u_l = tid>>4, seg = tid&15), loops t_l = 0..15.
    // pd fragment is loop-invariant -> registers.
    const int u_l = tid >> 4;
    const int seg = tid & 15;

    const float4 d0 = pd4[u_l][seg * 2];
    const float4 d1 = pd4[u_l][seg * 2 + 1];

    #pragma unroll
    for (int t_l = 0; t_l < 16; t_l++) {
        const float4 e0 = pe4[t_l][seg * 2];
        const float4 e1 = pe4[t_l][seg * 2 + 1];

        __half h[8];
        h[0] = __float2half_rn(fast_tanh(e0.x + d0.x));
        h[1] = __float2half_rn(fast_tanh(e0.y + d0.y));
        h[2] = __float2half_rn(fast_tanh(e0.z + d0.z));
        h[3] = __float2half_rn(fast_tanh(e0.w + d0.w));
        h[4] = __float2half_rn(fast_tanh(e1.x + d1.x));
        h[5] = __float2half_rn(fast_tanh(e1.y + d1.y));
        h[6] = __float2half_rn(fast_tanh(e1.z + d1.z));
        h[7] = __float2half_rn(fast_tanh(e1.w + d1.w));

        const size_t row = (size_t)b * TU + (t0 + t_l) * U_ + u0 + u_l;
        *(uint4*)&A[row * HH + h0 + seg * 8] = *(uint4*)h;
    }
}

// ---------------------------------------------------------------------------
// Stage 2: HMMA joint GEMM (R7 best variant, fp32 accumulators).
// BM=128, BN=128, BK=64; 128 threads = 4 warps (2M x 2N), warp tile 64x64.
// 3-stage cp.async pipeline, one sync/iter, 2 CTAs/SM.
// ---------------------------------------------------------------------------
#define STG_STRIDE 32768u
#define SMEM_TOTAL (STAGES * 32768)

__device__ __forceinline__ void load_buf(uint32_t sbuf,
                                         const __half* __restrict__ A,
                                         const __half* __restrict__ B,
                                         int m0, int n0, int k0)
{
    const int tid = threadIdx.x;
    #pragma unroll
    for (int i = 0; i < 8; i++) {
        int ci = tid + i * 128;
        int row = ci >> 3;
        int ck = ci & 7;
        uint32_t so = sbuf + row * 128 + ((ck ^ (row & 7)) << 4);
        CP_ASYNC16(so, A + (size_t)(m0 + row) * HH + k0 + ck * 8);
    }
    #pragma unroll
    for (int i = 0; i < 8; i++) {
        int ci = tid + i * 128;
        int row = ci >> 3;
        int ck = ci & 7;
        uint32_t so = sbuf + 16384u + row * 128 + ((ck ^ (row & 7)) << 4);
        CP_ASYNC16(so, B + (size_t)(n0 + row) * HH + k0 + ck * 8);
    }
}

__global__ void __launch_bounds__(128, 2)
joint_gemm(const __half* __restrict__ A,
           const __half* __restrict__ B,
           const float* __restrict__ b2,
           float* __restrict__ out)
{
    extern __shared__ __align__(1024) char smem[];
    const uint32_t sb = smem_u32(smem);

    const int tid  = threadIdx.x;
    const int lane = tid & 31;
    const int wid  = tid >> 5;
    const int wm   = wid & 1;
    const int wn   = wid >> 1;
    const int n0   = blockIdx.x * BN;
    const int m0   = blockIdx.y * BM;

    const int lml = lane & 15;
    const int lmh = lane >> 4;

    float acc[4][8][4];
    #pragma unroll
    for (int a = 0; a < 4; a++)
        #pragma unroll
        for (int n = 0; n < 8; n++)
            #pragma unroll
            for (int i = 0; i < 4; i++) acc[a][n][i] = 0.0f;

    load_buf(sb,              A, B, m0, n0, 0);
    CP_COMMIT();
    load_buf(sb + STG_STRIDE, A, B, m0, n0, BK);
    CP_COMMIT();
    CP_WAIT1();
    __syncthreads();

    for (int c = 0; c < KITERS; c++) {
        const uint32_t sbuf = sb + (uint32_t)(c % STAGES) * STG_STRIDE;

        if (c + 2 < KITERS) {
            load_buf(sb + (uint32_t)((c + 2) % STAGES) * STG_STRIDE,
                     A, B, m0, n0, (c + 2) * BK);
            CP_COMMIT();
        }

        #pragma unroll
        for (int ks = 0; ks < 4; ks++) {
            const int ck = 2 * ks + lmh;

            uint32_t af[4][4];
            #pragma unroll
            for (int a = 0; a < 4; a++) {
                uint32_t row = (uint32_t)(wm * 64 + a * 16 + lml);
                LDSM4(af[a][0], af[a][1], af[a][2], af[a][3],
                      sbuf + row * 128 + (uint32_t)((ck ^ (row & 7)) << 4));
            }
            uint32_t bf[4][4];
            #pragma unroll
            for (int p = 0; p < 4; p++) {
                uint32_t row = (uint32_t)(wn * 64 + p * 16 + lml);
                LDSM4(bf[p][0], bf[p][1], bf[p][2], bf[p][3],
                      sbuf + 16384u + row * 128 +
                      (uint32_t)((ck ^ (row & 7)) << 4));
            }
            #pragma unroll
            for (int a = 0; a < 4; a++)
                #pragma unroll
                for (int n = 0; n < 8; n++) {
                    int p = n >> 1, s = n & 1;
                    MMA16816(acc[a][n], af[a], bf[p][s], bf[p][s + 2]);
                }
        }

        if (c + 2 < KITERS) CP_WAIT1();
        else                CP_WAIT0();
        __syncthreads();
    }

    #pragma unroll
    for (int n = 0; n < 8; n++) {
        const int col = n0 + wn * 64 + n * 8 + (lane & 3) * 2;
        const float2 bb = *(const float2*)&b2[col];
        #pragma unroll
        for (int a = 0; a < 4; a++) {
            const size_t r0 = (size_t)m0 + wm * 64 + a * 16 + (lane >> 2);
            float2 o0 = { acc[a][n][0] + bb.x, acc[a][n][1] + bb.y };
            float2 o1 = { acc[a][n][2] + bb.x, acc[a][n][3] + bb.y };
            *(float2*)&out[r0 * VV + col]       = o0;
            *(float2*)&out[(r0 + 8) * VV + col] = o1;
        }
    }
}

// ---------------------------------------------------------------------------
// Launch: 3 kernels total
// ---------------------------------------------------------------------------
extern "C" void kernel_launch(void* const* d_in, const int* in_sizes, int n_in,
                              void* d_out, int out_size)
{
    const float* enc = (const float*)d_in[0];
    const float* dec = (const float*)d_in[1];
    const float* W1  = (const float*)d_in[2];
    const float* b1  = (const float*)d_in[3];
    const float* W2  = (const float*)d_in[4];
    const float* b2  = (const float*)d_in[5];
    float* out = (float*)d_out;

    float *pe = nullptr, *pd = nullptr;
    __half *ga = nullptr, *gb = nullptr;
    cudaGetSymbolAddress((void**)&pe, g_proj_e);
    cudaGetSymbolAddress((void**)&pd, g_proj_d);
    cudaGetSymbolAddress((void**)&ga, g_A);
    cudaGetSymbolAddress((void**)&gb, g_B);

    cudaFuncSetAttribute(joint_gemm,
                         cudaFuncAttributeMaxDynamicSharedMemorySize, SMEM_TOTAL);

    // projections + W2 transpose fused
    proj_and_w2<<<dim3(20, 47), 128>>>(enc, dec, W1, b1, W2, pe, pd, gb);
    // tiled tanh + fp16 pack
    prep_a<<<dim3(U_ / 16, T_ / 16, B_ * 5), 256>>>(ga);
    // joint GEMM
    joint_gemm<<<dim3(VV / BN, MTOT / BM), 128, SMEM_TOTAL>>>(ga, gb, b2, out);
}

// round 10
// speedup vs baseline: 1.1127x; 1.0083x over previous
#include <cuda_runtime.h>
#include <cuda_fp16.h>
#include <cstdint>

// ---------------------------------------------------------------------------
// Problem constants
// ---------------------------------------------------------------------------
#define B_ 4
#define T_ 160
#define U_ 80
#define DE 640
#define HH 640
#define VV 1024
#define TU (T_ * U_)          // 12800
#define MTOT (B_ * TU)        // 51200
#define KHALF 320             // split-K half length for projections

// Joint GEMM tiling
#define BM 128
#define BN 128
#define BK 64
#define KITERS (HH / BK)      // 10
#define STAGES 3

// ---------------------------------------------------------------------------
// Device scratch
// ---------------------------------------------------------------------------
__device__ float g_pe0[B_ * T_ * HH];
__device__ float g_pe1[B_ * T_ * HH];
__device__ float g_pd0[B_ * U_ * HH];
__device__ float g_pd1[B_ * U_ * HH];
__device__ __align__(16) __half g_A[(size_t)MTOT * HH];   // fp16(tanh(...))
__device__ __align__(16) __half g_B[VV * HH];             // W2^T fp16, [n][k]

// ---------------------------------------------------------------------------
// Helpers
// ---------------------------------------------------------------------------
__device__ __forceinline__ uint32_t smem_u32(const void* p) {
    uint32_t a;
    asm("{ .reg .u64 t; cvta.to.shared.u64 t, %1; cvt.u32.u64 %0, t; }"
        : "=r"(a) : "l"(p));
    return a;
}

__device__ __forceinline__ float fast_tanh(float x) {
    float e;
    asm("ex2.approx.f32 %0, %1;" : "=f"(e) : "f"(x * 2.885390081777927f));
    float r;
    asm("rcp.approx.f32 %0, %1;" : "=f"(r) : "f"(e + 1.0f));
    return fmaf(-2.0f, r, 1.0f);
}

#define CP_ASYNC16(saddr, gptr) \
    asm volatile("cp.async.cg.shared.global [%0], [%1], 16;" \
                 :: "r"(saddr), "l"(gptr))
#define CP_COMMIT()  asm volatile("cp.async.commit_group;" ::: "memory")
#define CP_WAIT1()   asm volatile("cp.async.wait_group 1;" ::: "memory")
#define CP_WAIT0()   asm volatile("cp.async.wait_group 0;" ::: "memory")

#define LDSM4(r0, r1, r2, r3, a) \
    asm volatile("ldmatrix.sync.aligned.m8n8.x4.shared.b16 {%0,%1,%2,%3}, [%4];" \
                 : "=r"(r0), "=r"(r1), "=r"(r2), "=r"(r3) : "r"(a))

#define MMA16816(d, a, b0, b1) \
    asm volatile("mma.sync.aligned.m16n8k16.row.col.f32.f16.f16.f32 " \
                 "{%0,%1,%2,%3}, {%4,%5,%6,%7}, {%8,%9}, {%0,%1,%2,%3};" \
                 : "+f"((d)[0]), "+f"((d)[1]), "+f"((d)[2]), "+f"((d)[3]) \
                 : "r"((a)[0]), "r"((a)[1]), "r"((a)[2]), "r"((a)[3]), \
                   "r"(b0), "r"(b1))

// ---------------------------------------------------------------------------
// Stage 1 (fused): split-K projections + W2 transpose. 256 threads.
// grid = (10, 46):
//   y 0..19 : enc proj, m-tile = y>>1, k-half = y&1   (BM=64, BN=64, BK=16)
//   y 20..29: dec proj, m-tile = (y-20)>>1, k-half = y&1
//   y 30..45: W2 transpose 64x64 tile, n0=(y-30)*64, k0=x*64
// ---------------------------------------------------------------------------
__global__ void __launch_bounds__(256)
proj_and_w2(const float* __restrict__ enc,
            const float* __restrict__ dec,
            const float* __restrict__ W1,
            const float* __restrict__ b1,
            const float* __restrict__ W2,
            float* __restrict__ pe0, float* __restrict__ pe1,
            float* __restrict__ pd0, float* __restrict__ pd1,
            __half* __restrict__ Bt)
{
    const int tid = threadIdx.x;

    if (blockIdx.y >= 30) {
        // ---- W2 transpose tile: Bt[n][k] = fp16(W2[k][n]), 64x64 ----
        __shared__ float tile[64][65];
        const int n0 = (blockIdx.y - 30) * 64;
        const int k0 = blockIdx.x * 64;
        const int x  = tid & 63;
        const int yq = tid >> 6;          // 0..3

        #pragma unroll
        for (int j = 0; j < 16; j++) {
            int r = yq + j * 4;
            tile[r][x] = W2[(size_t)(k0 + r) * VV + n0 + x];
        }
        __syncthreads();

        #pragma unroll
        for (int j = 0; j < 16; j++) {
            int ny = yq + j * 4;
            Bt[(size_t)(n0 + ny) * HH + k0 + x] = __float2half_rn(tile[x][ny]);
        }
        return;
    }

    // ---- projection path: BM=64, BN=64, BK=16, K-half = 320 (20 iters) ----
    __shared__ float As[16][65];
    __shared__ float Bs[16][64];

    const bool is_dec = (blockIdx.y >= 20);
    const int yy  = is_dec ? (blockIdx.y - 20) : blockIdx.y;
    const int m0  = (yy >> 1) * 64;
    const int kc  = yy & 1;               // k-half index
    const int kof = kc * KHALF;
    const int n0  = blockIdx.x * 64;

    const float* __restrict__ A    = is_dec ? dec : enc;
    const float* __restrict__ W    = is_dec ? (W1 + (size_t)DE * HH) : W1;
    const float* __restrict__ bias = (is_dec && kc == 0) ? b1 : nullptr;
    float* __restrict__ C = is_dec ? (kc ? pd1 : pd0) : (kc ? pe1 : pe0);

    // loaders: A 64 rows x 16 k = 256 float4 (1/thr); B 16 k x 64 n (1/thr)
    const int arow = tid >> 2;
    const int ak4  = (tid & 3) * 4;
    const int bk   = tid >> 4;
    const int bn   = (tid & 15) * 4;
    const int tx   = tid & 15;
    const int ty   = tid >> 4;

    float acc[4][4] = {};

    float4 av = *(const float4*)&A[(size_t)(m0 + arow) * DE + kof + ak4];
    float4 bv = *(const float4*)&W[(size_t)(kof + bk) * HH + n0 + bn];

    for (int k0 = 0; k0 < KHALF; k0 += 16) {
        As[ak4 + 0][arow] = av.x;
        As[ak4 + 1][arow] = av.y;
        As[ak4 + 2][arow] = av.z;
        As[ak4 + 3][arow] = av.w;
        *(float4*)&Bs[bk][bn] = bv;
        __syncthreads();

        if (k0 + 16 < KHALF) {
            av = *(const float4*)&A[(size_t)(m0 + arow) * DE + kof + k0 + 16 + ak4];
            bv = *(const float4*)&W[(size_t)(kof + k0 + 16 + bk) * HH + n0 + bn];
        }

        #pragma unroll
        for (int k = 0; k < 16; k++) {
            float a[4], b[4];
            #pragma unroll
            for (int j = 0; j < 4; j++) a[j] = As[k][ty * 4 + j];
            #pragma unroll
            for (int i = 0; i < 4; i++) b[i] = Bs[k][tx * 4 + i];
            #pragma unroll
            for (int j = 0; j < 4; j++)
                #pragma unroll
                for (int i = 0; i < 4; i++)
                    acc[j][i] = fmaf(a[j], b[i], acc[j][i]);
        }
        __syncthreads();
    }

    #pragma unroll
    for (int j = 0; j < 4; j++) {
        const int row = m0 + ty * 4 + j;
        #pragma unroll
        for (int i = 0; i < 4; i++) {
            float v = acc[j][i];
            if (bias) v += bias[n0 + tx * 4 + i];
            C[(size_t)row * HH + n0 + tx * 4 + i] = v;
        }
    }
}

// ---------------------------------------------------------------------------
// Stage 1.5: tiled A-prep, folding split-K partials.
// A = fp16(tanh((pe0+pe1) + (pd0+pd1))).  grid (U/16, T/16, B*5).
// ---------------------------------------------------------------------------
__global__ void __launch_bounds__(256)
prep_a(__half* __restrict__ A)
{
    __shared__ float4 pe4[16][33];
    __shared__ float4 pd4[16][33];

    const int u0 = blockIdx.x * 16;
    const int t0 = blockIdx.y * 16;
    const int b  = blockIdx.z / 5;
    const int h0 = (blockIdx.z - b * 5) * 128;

    const int tid = threadIdx.x;

    {
        const int r  = tid >> 4;
        const int c4 = tid & 15;
        const size_t eoff = (size_t)(b * T_ + t0 + r) * HH + h0;
        const size_t doff = (size_t)(b * U_ + u0 + r) * HH + h0;
        const float4* e0 = (const float4*)&g_pe0[eoff];
        const float4* e1 = (const float4*)&g_pe1[eoff];
        const float4* d0 = (const float4*)&g_pd0[doff];
        const float4* d1 = (const float4*)&g_pd1[doff];
        #pragma unroll
        for (int s = 0; s < 2; s++) {
            int c = c4 + s * 16;
            float4 ea = e0[c], eb = e1[c];
            float4 da = d0[c], db = d1[c];
            pe4[r][c] = make_float4(ea.x + eb.x, ea.y + eb.y,
                                    ea.z + eb.z, ea.w + eb.w);
            pd4[r][c] = make_float4(da.x + db.x, da.y + db.y,
                                    da.z + db.z, da.w + db.w);
        }
    }
    __syncthreads();

    const int u_l = tid >> 4;
    const int seg = tid & 15;

    const float4 d0 = pd4[u_l][seg * 2];
    const float4 d1 = pd4[u_l][seg * 2 + 1];

    #pragma unroll
    for (int t_l = 0; t_l < 16; t_l++) {
        const float4 e0 = pe4[t_l][seg * 2];
        const float4 e1 = pe4[t_l][seg * 2 + 1];

        __half h[8];
        h[0] = __float2half_rn(fast_tanh(e0.x + d0.x));
        h[1] = __float2half_rn(fast_tanh(e0.y + d0.y));
        h[2] = __float2half_rn(fast_tanh(e0.z + d0.z));
        h[3] = __float2half_rn(fast_tanh(e0.w + d0.w));
        h[4] = __float2half_rn(fast_tanh(e1.x + d1.x));
        h[5] = __float2half_rn(fast_tanh(e1.y + d1.y));
        h[6] = __float2half_rn(fast_tanh(e1.z + d1.z));
        h[7] = __float2half_rn(fast_tanh(e1.w + d1.w));

        const size_t row = (size_t)b * TU + (t0 + t_l) * U_ + u0 + u_l;
        *(uint4*)&A[row * HH + h0 + seg * 8] = *(uint4*)h;
    }
}

// ---------------------------------------------------------------------------
// Stage 2: HMMA joint GEMM (best measured variant — unchanged).
// BM=128, BN=128, BK=64; 128 threads = 4 warps (2M x 2N), warp tile 64x64.
// 3-stage cp.async pipeline, one sync/iter, 2 CTAs/SM.
// ---------------------------------------------------------------------------
#define STG_STRIDE 32768u
#define SMEM_TOTAL (STAGES * 32768)

__device__ __forceinline__ void load_buf(uint32_t sbuf,
                                         const __half* __restrict__ A,
                                         const __half* __restrict__ B,
                                         int m0, int n0, int k0)
{
    const int tid = threadIdx.x;
    #pragma unroll
    for (int i = 0; i < 8; i++) {
        int ci = tid + i * 128;
        int row = ci >> 3;
        int ck = ci & 7;
        uint32_t so = sbuf + row * 128 + ((ck ^ (row & 7)) << 4);
        CP_ASYNC16(so, A + (size_t)(m0 + row) * HH + k0 + ck * 8);
    }
    #pragma unroll
    for (int i = 0; i < 8; i++) {
        int ci = tid + i * 128;
        int row = ci >> 3;
        int ck = ci & 7;
        uint32_t so = sbuf + 16384u + row * 128 + ((ck ^ (row & 7)) << 4);
        CP_ASYNC16(so, B + (size_t)(n0 + row) * HH + k0 + ck * 8);
    }
}

__global__ void __launch_bounds__(128, 2)
joint_gemm(const __half* __restrict__ A,
           const __half* __restrict__ B,
           const float* __restrict__ b2,
           float* __restrict__ out)
{
    extern __shared__ __align__(1024) char smem[];
    const uint32_t sb = smem_u32(smem);

    const int tid  = threadIdx.x;
    const int lane = tid & 31;
    const int wid  = tid >> 5;
    const int wm   = wid & 1;
    const int wn   = wid >> 1;
    const int n0   = blockIdx.x * BN;
    const int m0   = blockIdx.y * BM;

    const int lml = lane & 15;
    const int lmh = lane >> 4;

    float acc[4][8][4];
    #pragma unroll
    for (int a = 0; a < 4; a++)
        #pragma unroll
        for (int n = 0; n < 8; n++)
            #pragma unroll
            for (int i = 0; i < 4; i++) acc[a][n][i] = 0.0f;

    load_buf(sb,              A, B, m0, n0, 0);
    CP_COMMIT();
    load_buf(sb + STG_STRIDE, A, B, m0, n0, BK);
    CP_COMMIT();
    CP_WAIT1();
    __syncthreads();

    for (int c = 0; c < KITERS; c++) {
        const uint32_t sbuf = sb + (uint32_t)(c % STAGES) * STG_STRIDE;

        if (c + 2 < KITERS) {
            load_buf(sb + (uint32_t)((c + 2) % STAGES) * STG_STRIDE,
                     A, B, m0, n0, (c + 2) * BK);
            CP_COMMIT();
        }

        #pragma unroll
        for (int ks = 0; ks < 4; ks++) {
            const int ck = 2 * ks + lmh;

            uint32_t af[4][4];
            #pragma unroll
            for (int a = 0; a < 4; a++) {
                uint32_t row = (uint32_t)(wm * 64 + a * 16 + lml);
                LDSM4(af[a][0], af[a][1], af[a][2], af[a][3],
                      sbuf + row * 128 + (uint32_t)((ck ^ (row & 7)) << 4));
            }
            uint32_t bf[4][4];
            #pragma unroll
            for (int p = 0; p < 4; p++) {
                uint32_t row = (uint32_t)(wn * 64 + p * 16 + lml);
                LDSM4(bf[p][0], bf[p][1], bf[p][2], bf[p][3],
                      sbuf + 16384u + row * 128 +
                      (uint32_t)((ck ^ (row & 7)) << 4));
            }
            #pragma unroll
            for (int a = 0; a < 4; a++)
                #pragma unroll
                for (int n = 0; n < 8; n++) {
                    int p = n >> 1, s = n & 1;
                    MMA16816(acc[a][n], af[a], bf[p][s], bf[p][s + 2]);
                }
        }

        if (c + 2 < KITERS) CP_WAIT1();
        else                CP_WAIT0();
        __syncthreads();
    }

    #pragma unroll
    for (int n = 0; n < 8; n++) {
        const int col = n0 + wn * 64 + n * 8 + (lane & 3) * 2;
        const float2 bb = *(const float2*)&b2[col];
        #pragma unroll
        for (int a = 0; a < 4; a++) {
            const size_t r0 = (size_t)m0 + wm * 64 + a * 16 + (lane >> 2);
            float2 o0 = { acc[a][n][0] + bb.x, acc[a][n][1] + bb.y };
            float2 o1 = { acc[a][n][2] + bb.x, acc[a][n][3] + bb.y };
            *(float2*)&out[r0 * VV + col]       = o0;
            *(float2*)&out[(r0 + 8) * VV + col] = o1;
        }
    }
}

// ---------------------------------------------------------------------------
// Launch: 3 kernels total
// ---------------------------------------------------------------------------
extern "C" void kernel_launch(void* const* d_in, const int* in_sizes, int n_in,
                              void* d_out, int out_size)
{
    const float* enc = (const float*)d_in[0];
    const float* dec = (const float*)d_in[1];
    const float* W1  = (const float*)d_in[2];
    const float* b1  = (const float*)d_in[3];
    const float* W2  = (const float*)d_in[4];
    const float* b2  = (const float*)d_in[5];
    float* out = (float*)d_out;

    float *pe0 = nullptr, *pe1 = nullptr, *pd0 = nullptr, *pd1 = nullptr;
    __half *ga = nullptr, *gb = nullptr;
    cudaGetSymbolAddress((void**)&pe0, g_pe0);
    cudaGetSymbolAddress((void**)&pe1, g_pe1);
    cudaGetSymbolAddress((void**)&pd0, g_pd0);
    cudaGetSymbolAddress((void**)&pd1, g_pd1);
    cudaGetSymbolAddress((void**)&ga, g_A);
    cudaGetSymbolAddress((void**)&gb, g_B);

    cudaFuncSetAttribute(joint_gemm,
                         cudaFuncAttributeMaxDynamicSharedMemorySize, SMEM_TOTAL);

    // split-K projections + W2 transpose fused
    proj_and_w2<<<dim3(10, 46), 256>>>(enc, dec, W1, b1, W2,
                                       pe0, pe1, pd0, pd1, gb);
    // tiled tanh + fp16 pack (folds split-K partials)
    prep_a<<<dim3(U_ / 16, T_ / 16, B_ * 5), 256>>>(ga);
    // joint GEMM
    joint_gemm<<<dim3(VV / BN, MTOT / BM), 128, SMEM_TOTAL>>>(ga, gb, b2, out);
}

// round 11
// speedup vs baseline: 1.2298x; 1.1053x over previous
#include <cuda_runtime.h>
#include <cuda_fp16.h>
#include <cstdint>

// ---------------------------------------------------------------------------
// Problem constants
// ---------------------------------------------------------------------------
#define B_ 4
#define T_ 160
#define U_ 80
#define DE 640
#define DTOT 1280
#define HH 640
#define VV 1024
#define TU (T_ * U_)          // 12800
#define MTOT (B_ * TU)        // 51200

// Joint GEMM tiling
#define BM 128
#define BN 128
#define BK 64
#define KITERS (HH / BK)      // 10
#define STAGES 3

// ---------------------------------------------------------------------------
// Device scratch
// ---------------------------------------------------------------------------
__device__ float g_pe[B_ * T_ * HH];
__device__ float g_pd[B_ * U_ * HH];
__device__ __align__(16) __half g_Ae[B_ * T_ * DE];       // fp16(enc)
__device__ __align__(16) __half g_Ad[B_ * U_ * DE];       // fp16(dec)
__device__ __align__(16) __half g_W1T[HH * DTOT];         // W1^T [h][d]
__device__ __align__(16) __half g_A[(size_t)MTOT * HH];   // fp16(tanh(...))
__device__ __align__(16) __half g_B[VV * HH];             // W2^T fp16 [n][k]

// ---------------------------------------------------------------------------
// Helpers
// ---------------------------------------------------------------------------
__device__ __forceinline__ uint32_t smem_u32(const void* p) {
    uint32_t a;
    asm("{ .reg .u64 t; cvta.to.shared.u64 t, %1; cvt.u32.u64 %0, t; }"
        : "=r"(a) : "l"(p));
    return a;
}

__device__ __forceinline__ float fast_tanh(float x) {
    float e;
    asm("ex2.approx.f32 %0, %1;" : "=f"(e) : "f"(x * 2.885390081777927f));
    float r;
    asm("rcp.approx.f32 %0, %1;" : "=f"(r) : "f"(e + 1.0f));
    return fmaf(-2.0f, r, 1.0f);
}

#define CP_ASYNC16(saddr, gptr) \
    asm volatile("cp.async.cg.shared.global [%0], [%1], 16;" \
                 :: "r"(saddr), "l"(gptr))
#define CP_COMMIT()  asm volatile("cp.async.commit_group;" ::: "memory")
#define CP_WAIT1()   asm volatile("cp.async.wait_group 1;" ::: "memory")
#define CP_WAIT0()   asm volatile("cp.async.wait_group 0;" ::: "memory")

#define LDSM4(r0, r1, r2, r3, a) \
    asm volatile("ldmatrix.sync.aligned.m8n8.x4.shared.b16 {%0,%1,%2,%3}, [%4];" \
                 : "=r"(r0), "=r"(r1), "=r"(r2), "=r"(r3) : "r"(a))

#define MMA16816(d, a, b0, b1) \
    asm volatile("mma.sync.aligned.m16n8k16.row.col.f32.f16.f16.f32 " \
                 "{%0,%1,%2,%3}, {%4,%5,%6,%7}, {%8,%9}, {%0,%1,%2,%3};" \
                 : "+f"((d)[0]), "+f"((d)[1]), "+f"((d)[2]), "+f"((d)[3]) \
                 : "r"((a)[0]), "r"((a)[1]), "r"((a)[2]), "r"((a)[3]), \
                   "r"(b0), "r"(b1))

// ---------------------------------------------------------------------------
// Stage 0: prep_static — one launch:
//   bx 0..159   : W2 transpose 64x64 tile -> g_B  (n-tile = bx&15, k = bx>>4)
//   bx 160..359 : W1 transpose 64x64 tile -> g_W1T (h-tile = t%10, d = t/10)
//   bx 360..759 : enc fp32->fp16 copy (400 x 1024 elems)
//   bx 760..959 : dec fp32->fp16 copy (200 x 1024 elems)
// ---------------------------------------------------------------------------
__global__ void __launch_bounds__(256)
prep_static(const float* __restrict__ enc,
            const float* __restrict__ dec,
            const float* __restrict__ W1,
            const float* __restrict__ W2,
            __half* __restrict__ Ae,
            __half* __restrict__ Ad,
            __half* __restrict__ W1T,
            __half* __restrict__ Bt)
{
    __shared__ float tile[64][65];
    const int tid = threadIdx.x;
    const int bx  = blockIdx.x;

    if (bx < 360) {
        const int x  = tid & 63;
        const int yq = tid >> 6;          // 0..3
        if (bx < 160) {                   // W2: [640,1024] -> g_B[n][k]
            const int n0 = (bx & 15) * 64;
            const int k0 = (bx >> 4) * 64;
            #pragma unroll
            for (int j = 0; j < 16; j++) {
                int r = yq + j * 4;
                tile[r][x] = W2[(size_t)(k0 + r) * VV + n0 + x];
            }
            __syncthreads();
            #pragma unroll
            for (int j = 0; j < 16; j++) {
                int ny = yq + j * 4;
                Bt[(size_t)(n0 + ny) * HH + k0 + x] =
                    __float2half_rn(tile[x][ny]);
            }
        } else {                          // W1: [1280,640] -> g_W1T[h][d]
            const int t  = bx - 160;
            const int h0 = (t % 10) * 64;
            const int d0 = (t / 10) * 64;
            #pragma unroll
            for (int j = 0; j < 16; j++) {
                int r = yq + j * 4;
                tile[r][x] = W1[(size_t)(d0 + r) * HH + h0 + x];
            }
            __syncthreads();
            #pragma unroll
            for (int j = 0; j < 16; j++) {
                int ny = yq + j * 4;
                W1T[(size_t)(h0 + ny) * DTOT + d0 + x] =
                    __float2half_rn(tile[x][ny]);
            }
        }
        return;
    }

    // fp32 -> fp16 copies, 1024 elems per block, vectorized x4
    const int cb = bx - 360;
    const float* __restrict__ src;
    __half* __restrict__ dst;
    size_t off;
    if (cb < 400) { src = enc; dst = Ae; off = (size_t)cb * 1024; }
    else          { src = dec; dst = Ad; off = (size_t)(cb - 400) * 1024; }

    const size_t idx = off + tid * 4;
    float4 v = *(const float4*)&src[idx];
    __half h[4];
    h[0] = __float2half_rn(v.x);
    h[1] = __float2half_rn(v.y);
    h[2] = __float2half_rn(v.z);
    h[3] = __float2half_rn(v.w);
    *(uint2*)&dst[idx] = *(uint2*)h;
}

// ---------------------------------------------------------------------------
// Stage 1: HMMA projection GEMM.
// pe[640,640] = Ae @ W1T[:, 0:640]^T ;  pd[320,640] = Ad @ W1T[:,640:1280]^T + b1
// BM=64, BN=128, BK=64, K=640; 128 threads = 4 warps (1M x 4N), warp 64x32.
// grid (5, 15): y 0..9 enc m-tiles, 10..14 dec m-tiles. 3-stage cp.async.
// smem/stage: A 8KB @0, B 16KB @8K; stride 24KB; total 72KB.
// ---------------------------------------------------------------------------
#define PSTG 24576u
#define PROJ_SMEM (3 * 24576)

__device__ __forceinline__ void proj_load(uint32_t sbuf,
                                          const __half* __restrict__ A,
                                          const __half* __restrict__ W1T,
                                          int m0, int n0, int dof, int k0)
{
    const int tid = threadIdx.x;
    // A: 64 rows x 8 chunks = 512, 4/thread (row stride DE)
    #pragma unroll
    for (int i = 0; i < 4; i++) {
        int ci = tid + i * 128;
        int row = ci >> 3;
        int ck = ci & 7;
        uint32_t so = sbuf + row * 128 + ((ck ^ (row & 7)) << 4);
        CP_ASYNC16(so, A + (size_t)(m0 + row) * DE + k0 + ck * 8);
    }
    // B: 128 rows x 8 chunks = 1024, 8/thread (row stride DTOT)
    #pragma unroll
    for (int i = 0; i < 8; i++) {
        int ci = tid + i * 128;
        int row = ci >> 3;
        int ck = ci & 7;
        uint32_t so = sbuf + 8192u + row * 128 + ((ck ^ (row & 7)) << 4);
        CP_ASYNC16(so, W1T + (size_t)(n0 + row) * DTOT + dof + k0 + ck * 8);
    }
}

__global__ void __launch_bounds__(128, 2)
proj_gemm(const __half* __restrict__ Ae,
          const __half* __restrict__ Ad,
          const __half* __restrict__ W1T,
          const float* __restrict__ b1,
          float* __restrict__ pe,
          float* __restrict__ pd)
{
    extern __shared__ __align__(1024) char smem[];
    const uint32_t sb = smem_u32(smem);

    const int tid  = threadIdx.x;
    const int lane = tid & 31;
    const int wn   = tid >> 5;            // 4 warps over 128 n-cols
    const int n0   = blockIdx.x * 128;
    const bool is_dec = (blockIdx.y >= 10);
    const int m0   = (is_dec ? (blockIdx.y - 10) : blockIdx.y) * 64;
    const int dof  = is_dec ? DE : 0;

    const __half* __restrict__ A = is_dec ? Ad : Ae;
    float* __restrict__ C        = is_dec ? pd : pe;

    const int lml = lane & 15;
    const int lmh = lane >> 4;

    float acc[4][4][4];
    #pragma unroll
    for (int a = 0; a < 4; a++)
        #pragma unroll
        for (int n = 0; n < 4; n++)
            #pragma unroll
            for (int i = 0; i < 4; i++) acc[a][n][i] = 0.0f;

    proj_load(sb,        A, W1T, m0, n0, dof, 0);
    CP_COMMIT();
    proj_load(sb + PSTG, A, W1T, m0, n0, dof, BK);
    CP_COMMIT();
    CP_WAIT1();
    __syncthreads();

    for (int c = 0; c < 10; c++) {        // K = 640 / BK
        const uint32_t sbuf = sb + (uint32_t)(c % STAGES) * PSTG;

        if (c + 2 < 10) {
            proj_load(sb + (uint32_t)((c + 2) % STAGES) * PSTG,
                      A, W1T, m0, n0, dof, (c + 2) * BK);
            CP_COMMIT();
        }

        #pragma unroll
        for (int ks = 0; ks < 4; ks++) {
            const int ck = 2 * ks + lmh;

            uint32_t af[4][4];
            #pragma unroll
            for (int a = 0; a < 4; a++) {
                uint32_t row = (uint32_t)(a * 16 + lml);
                LDSM4(af[a][0], af[a][1], af[a][2], af[a][3],
                      sbuf + row * 128 + (uint32_t)((ck ^ (row & 7)) << 4));
            }
            uint32_t bf[2][4];
            #pragma unroll
            for (int p = 0; p < 2; p++) {
                uint32_t row = (uint32_t)(wn * 32 + p * 16 + lml);
                LDSM4(bf[p][0], bf[p][1], bf[p][2], bf[p][3],
                      sbuf + 8192u + row * 128 +
                      (uint32_t)((ck ^ (row & 7)) << 4));
            }
            #pragma unroll
            for (int a = 0; a < 4; a++)
                #pragma unroll
                for (int n = 0; n < 4; n++) {
                    int p = n >> 1, s = n & 1;
                    MMA16816(acc[a][n], af[a], bf[p][s], bf[p][s + 2]);
                }
        }

        if (c + 2 < 10) CP_WAIT1();
        else            CP_WAIT0();
        __syncthreads();
    }

    // epilogue: fp32 out, +b1 for dec
    #pragma unroll
    for (int n = 0; n < 4; n++) {
        const int col = n0 + wn * 32 + n * 8 + (lane & 3) * 2;
        float2 bb = make_float2(0.0f, 0.0f);
        if (is_dec) bb = *(const float2*)&b1[col];
        #pragma unroll
        for (int a = 0; a < 4; a++) {
            const int r0 = m0 + a * 16 + (lane >> 2);
            float2 o0 = { acc[a][n][0] + bb.x, acc[a][n][1] + bb.y };
            float2 o1 = { acc[a][n][2] + bb.x, acc[a][n][3] + bb.y };
            *(float2*)&C[(size_t)r0 * HH + col]       = o0;
            *(float2*)&C[(size_t)(r0 + 8) * HH + col] = o1;
        }
    }
}

// ---------------------------------------------------------------------------
// Stage 1.5: tiled A-prep. A = fp16(tanh(pe + pd)). grid (U/16, T/16, B*5).
// ---------------------------------------------------------------------------
__global__ void __launch_bounds__(256)
prep_a(__half* __restrict__ A)
{
    __shared__ float4 pe4[16][33];
    __shared__ float4 pd4[16][33];

    const int u0 = blockIdx.x * 16;
    const int t0 = blockIdx.y * 16;
    const int b  = blockIdx.z / 5;
    const int h0 = (blockIdx.z - b * 5) * 128;

    const int tid = threadIdx.x;

    {
        const int r  = tid >> 4;
        const int c4 = tid & 15;
        const float4* pe_g = (const float4*)&g_pe[(size_t)(b * T_ + t0 + r) * HH + h0];
        const float4* pd_g = (const float4*)&g_pd[(size_t)(b * U_ + u0 + r) * HH + h0];
        pe4[r][c4]      = pe_g[c4];
        pe4[r][c4 + 16] = pe_g[c4 + 16];
        pd4[r][c4]      = pd_g[c4];
        pd4[r][c4 + 16] = pd_g[c4 + 16];
    }
    __syncthreads();

    const int u_l = tid >> 4;
    const int seg = tid & 15;

    const float4 d0 = pd4[u_l][seg * 2];
    const float4 d1 = pd4[u_l][seg * 2 + 1];

    #pragma unroll
    for (int t_l = 0; t_l < 16; t_l++) {
        const float4 e0 = pe4[t_l][seg * 2];
        const float4 e1 = pe4[t_l][seg * 2 + 1];

        __half h[8];
        h[0] = __float2half_rn(fast_tanh(e0.x + d0.x));
        h[1] = __float2half_rn(fast_tanh(e0.y + d0.y));
        h[2] = __float2half_rn(fast_tanh(e0.z + d0.z));
        h[3] = __float2half_rn(fast_tanh(e0.w + d0.w));
        h[4] = __float2half_rn(fast_tanh(e1.x + d1.x));
        h[5] = __float2half_rn(fast_tanh(e1.y + d1.y));
        h[6] = __float2half_rn(fast_tanh(e1.z + d1.z));
        h[7] = __float2half_rn(fast_tanh(e1.w + d1.w));

        const size_t row = (size_t)b * TU + (t0 + t_l) * U_ + u0 + u_l;
        *(uint4*)&A[row * HH + h0 + seg * 8] = *(uint4*)h;
    }
}

// ---------------------------------------------------------------------------
// Stage 2: HMMA joint GEMM (best measured variant — unchanged).
// ---------------------------------------------------------------------------
#define STG_STRIDE 32768u
#define SMEM_TOTAL (STAGES * 32768)

__device__ __forceinline__ void load_buf(uint32_t sbuf,
                                         const __half* __restrict__ A,
                                         const __half* __restrict__ B,
                                         int m0, int n0, int k0)
{
    const int tid = threadIdx.x;
    #pragma unroll
    for (int i = 0; i < 8; i++) {
        int ci = tid + i * 128;
        int row = ci >> 3;
        int ck = ci & 7;
        uint32_t so = sbuf + row * 128 + ((ck ^ (row & 7)) << 4);
        CP_ASYNC16(so, A + (size_t)(m0 + row) * HH + k0 + ck * 8);
    }
    #pragma unroll
    for (int i = 0; i < 8; i++) {
        int ci = tid + i * 128;
        int row = ci >> 3;
        int ck = ci & 7;
        uint32_t so = sbuf + 16384u + row * 128 + ((ck ^ (row & 7)) << 4);
        CP_ASYNC16(so, B + (size_t)(n0 + row) * HH + k0 + ck * 8);
    }
}

__global__ void __launch_bounds__(128, 2)
joint_gemm(const __half* __restrict__ A,
           const __half* __restrict__ B,
           const float* __restrict__ b2,
           float* __restrict__ out)
{
    extern __shared__ __align__(1024) char smem[];
    const uint32_t sb = smem_u32(smem);

    const int tid  = threadIdx.x;
    const int lane = tid & 31;
    const int wid  = tid >> 5;
    const int wm   = wid & 1;
    const int wn   = wid >> 1;
    const int n0   = blockIdx.x * BN;
    const int m0   = blockIdx.y * BM;

    const int lml = lane & 15;
    const int lmh = lane >> 4;

    float acc[4][8][4];
    #pragma unroll
    for (int a = 0; a < 4; a++)
        #pragma unroll
        for (int n = 0; n < 8; n++)
            #pragma unroll
            for (int i = 0; i < 4; i++) acc[a][n][i] = 0.0f;

    load_buf(sb,              A, B, m0, n0, 0);
    CP_COMMIT();
    load_buf(sb + STG_STRIDE, A, B, m0, n0, BK);
    CP_COMMIT();
    CP_WAIT1();
    __syncthreads();

    for (int c = 0; c < KITERS; c++) {
        const uint32_t sbuf = sb + (uint32_t)(c % STAGES) * STG_STRIDE;

        if (c + 2 < KITERS) {
            load_buf(sb + (uint32_t)((c + 2) % STAGES) * STG_STRIDE,
                     A, B, m0, n0, (c + 2) * BK);
            CP_COMMIT();
        }

        #pragma unroll
        for (int ks = 0; ks < 4; ks++) {
            const int ck = 2 * ks + lmh;

            uint32_t af[4][4];
            #pragma unroll
            for (int a = 0; a < 4; a++) {
                uint32_t row = (uint32_t)(wm * 64 + a * 16 + lml);
                LDSM4(af[a][0], af[a][1], af[a][2], af[a][3],
                      sbuf + row * 128 + (uint32_t)((ck ^ (row & 7)) << 4));
            }
            uint32_t bf[4][4];
            #pragma unroll
            for (int p = 0; p < 4; p++) {
                uint32_t row = (uint32_t)(wn * 64 + p * 16 + lml);
                LDSM4(bf[p][0], bf[p][1], bf[p][2], bf[p][3],
                      sbuf + 16384u + row * 128 +
                      (uint32_t)((ck ^ (row & 7)) << 4));
            }
            #pragma unroll
            for (int a = 0; a < 4; a++)
                #pragma unroll
                for (int n = 0; n < 8; n++) {
                    int p = n >> 1, s = n & 1;
                    MMA16816(acc[a][n], af[a], bf[p][s], bf[p][s + 2]);
                }
        }

        if (c + 2 < KITERS) CP_WAIT1();
        else                CP_WAIT0();
        __syncthreads();
    }

    #pragma unroll
    for (int n = 0; n < 8; n++) {
        const int col = n0 + wn * 64 + n * 8 + (lane & 3) * 2;
        const float2 bb = *(const float2*)&b2[col];
        #pragma unroll
        for (int a = 0; a < 4; a++) {
            const size_t r0 = (size_t)m0 + wm * 64 + a * 16 + (lane >> 2);
            float2 o0 = { acc[a][n][0] + bb.x, acc[a][n][1] + bb.y };
            float2 o1 = { acc[a][n][2] + bb.x, acc[a][n][3] + bb.y };
            *(float2*)&out[r0 * VV + col]       = o0;
            *(float2*)&out[(r0 + 8) * VV + col] = o1;
        }
    }
}

// ---------------------------------------------------------------------------
// Launch: 4 kernels
// ---------------------------------------------------------------------------
extern "C" void kernel_launch(void* const* d_in, const int* in_sizes, int n_in,
                              void* d_out, int out_size)
{
    const float* enc = (const float*)d_in[0];
    const float* dec = (const float*)d_in[1];
    const float* W1  = (const float*)d_in[2];
    const float* b1  = (const float*)d_in[3];
    const float* W2  = (const float*)d_in[4];
    const float* b2  = (const float*)d_in[5];
    float* out = (float*)d_out;

    float *pe = nullptr, *pd = nullptr;
    __half *ga = nullptr, *gb = nullptr, *gae = nullptr, *gad = nullptr,
           *gw1t = nullptr;
    cudaGetSymbolAddress((void**)&pe,   g_pe);
    cudaGetSymbolAddress((void**)&pd,   g_pd);
    cudaGetSymbolAddress((void**)&ga,   g_A);
    cudaGetSymbolAddress((void**)&gb,   g_B);
    cudaGetSymbolAddress((void**)&gae,  g_Ae);
    cudaGetSymbolAddress((void**)&gad,  g_Ad);
    cudaGetSymbolAddress((void**)&gw1t, g_W1T);

    cudaFuncSetAttribute(joint_gemm,
                         cudaFuncAttributeMaxDynamicSharedMemorySize, SMEM_TOTAL);
    cudaFuncSetAttribute(proj_gemm,
                         cudaFuncAttributeMaxDynamicSharedMemorySize, PROJ_SMEM);

    // transposes + fp16 conversions (one launch)
    prep_static<<<960, 256>>>(enc, dec, W1, W2, gae, gad, gw1t, gb);
    // tensor-core projections (+b1 on dec)
    proj_gemm<<<dim3(HH / 128, 15), 128, PROJ_SMEM>>>(gae, gad, gw1t, b1, pe, pd);
    // tiled tanh + fp16 pack
    prep_a<<<dim3(U_ / 16, T_ / 16, B_ * 5), 256>>>(ga);
    // joint GEMM
    joint_gemm<<<dim3(VV / BN, MTOT / BM), 128, SMEM_TOTAL>>>(ga, gb, b2, out);
}

// round 12
// speedup vs baseline: 1.2307x; 1.0007x over previous
#include <cuda_runtime.h>
#include <cuda_fp16.h>
#include <cstdint>

// ---------------------------------------------------------------------------
// Problem constants
// ---------------------------------------------------------------------------
#define B_ 4
#define T_ 160
#define U_ 80
#define DE 640
#define DTOT 1280
#define HH 640
#define VV 1024
#define TU (T_ * U_)          // 12800
#define MTOT (B_ * TU)        // 51200

// Joint GEMM tiling
#define BM 128
#define BN 128
#define BK 64
#define KITERS (HH / BK)      // 10
#define STAGES 3

// ---------------------------------------------------------------------------
// Device scratch
// ---------------------------------------------------------------------------
__device__ float g_pe[B_ * T_ * HH];
__device__ float g_pd[B_ * U_ * HH];
__device__ __align__(16) __half g_Ae[B_ * T_ * DE];       // fp16(enc)
__device__ __align__(16) __half g_Ad[B_ * U_ * DE];       // fp16(dec)
__device__ __align__(16) __half g_W1T[HH * DTOT];         // W1^T [h][d]
__device__ __align__(16) __half g_A[(size_t)MTOT * HH];   // fp16(tanh(...))
__device__ __align__(16) __half g_B[VV * HH];             // W2^T fp16 [n][k]

// ---------------------------------------------------------------------------
// Helpers
// ---------------------------------------------------------------------------
__device__ __forceinline__ uint32_t smem_u32(const void* p) {
    uint32_t a;
    asm("{ .reg .u64 t; cvta.to.shared.u64 t, %1; cvt.u32.u64 %0, t; }"
        : "=r"(a) : "l"(p));
    return a;
}

__device__ __forceinline__ float fast_tanh(float x) {
    float e;
    asm("ex2.approx.f32 %0, %1;" : "=f"(e) : "f"(x * 2.885390081777927f));
    float r;
    asm("rcp.approx.f32 %0, %1;" : "=f"(r) : "f"(e + 1.0f));
    return fmaf(-2.0f, r, 1.0f);
}

#define CP_ASYNC16(saddr, gptr) \
    asm volatile("cp.async.cg.shared.global [%0], [%1], 16;" \
                 :: "r"(saddr), "l"(gptr))
#define CP_COMMIT()  asm volatile("cp.async.commit_group;" ::: "memory")
#define CP_WAIT1()   asm volatile("cp.async.wait_group 1;" ::: "memory")
#define CP_WAIT0()   asm volatile("cp.async.wait_group 0;" ::: "memory")

#define LDSM4(r0, r1, r2, r3, a) \
    asm volatile("ldmatrix.sync.aligned.m8n8.x4.shared.b16 {%0,%1,%2,%3}, [%4];" \
                 : "=r"(r0), "=r"(r1), "=r"(r2), "=r"(r3) : "r"(a))

#define MMA16816(d, a, b0, b1) \
    asm volatile("mma.sync.aligned.m16n8k16.row.col.f32.f16.f16.f32 " \
                 "{%0,%1,%2,%3}, {%4,%5,%6,%7}, {%8,%9}, {%0,%1,%2,%3};" \
                 : "+f"((d)[0]), "+f"((d)[1]), "+f"((d)[2]), "+f"((d)[3]) \
                 : "r"((a)[0]), "r"((a)[1]), "r"((a)[2]), "r"((a)[3]), \
                   "r"(b0), "r"(b1))

// ---------------------------------------------------------------------------
// Stage 0: prep_static — W1 transpose + enc/dec fp16 conversion. 350 CTAs.
//   bx 0..199   : W1 transpose 64x64 tile -> g_W1T (h-tile = bx%10, d = bx/10)
//   bx 200..299 : enc fp32->fp16 copy (4096 elems/block)
//   bx 300..349 : dec fp32->fp16 copy (4096 elems/block)
// ---------------------------------------------------------------------------
__global__ void __launch_bounds__(256)
prep_static(const float* __restrict__ enc,
            const float* __restrict__ dec,
            const float* __restrict__ W1,
            __half* __restrict__ Ae,
            __half* __restrict__ Ad,
            __half* __restrict__ W1T)
{
    const int tid = threadIdx.x;
    const int bx  = blockIdx.x;

    if (bx < 200) {                       // W1: [1280,640] -> g_W1T[h][d]
        __shared__ float tile[64][65];
        const int h0 = (bx % 10) * 64;
        const int d0 = (bx / 10) * 64;
        const int x  = tid & 63;
        const int yq = tid >> 6;          // 0..3
        #pragma unroll
        for (int j = 0; j < 16; j++) {
            int r = yq + j * 4;
            tile[r][x] = W1[(size_t)(d0 + r) * HH + h0 + x];
        }
        __syncthreads();
        #pragma unroll
        for (int j = 0; j < 16; j++) {
            int ny = yq + j * 4;
            W1T[(size_t)(h0 + ny) * DTOT + d0 + x] =
                __float2half_rn(tile[x][ny]);
        }
        return;
    }

    // fp32 -> fp16 copies, 4096 elems per block (4 x float4 per thread)
    const int cb = bx - 200;
    const float* __restrict__ src;
    __half* __restrict__ dst;
    size_t off;
    if (cb < 100) { src = enc; dst = Ae; off = (size_t)cb * 4096; }
    else          { src = dec; dst = Ad; off = (size_t)(cb - 100) * 4096; }

    #pragma unroll
    for (int i = 0; i < 4; i++) {
        const size_t idx = off + (size_t)i * 1024 + tid * 4;
        float4 v = *(const float4*)&src[idx];
        __half h[4];
        h[0] = __float2half_rn(v.x);
        h[1] = __float2half_rn(v.y);
        h[2] = __float2half_rn(v.z);
        h[3] = __float2half_rn(v.w);
        *(uint2*)&dst[idx] = *(uint2*)h;
    }
}

// ---------------------------------------------------------------------------
// Stage 1: HMMA projection GEMM + W2 transpose (overlapped in one grid).
// grid (5, 47):
//   y 0..9  : enc proj m-tiles   pe = Ae @ W1T[:,0:640]^T
//   y 10..14: dec proj m-tiles   pd = Ad @ W1T[:,640:1280]^T + b1
//   y 15..46: W2 transpose tiles tt = (y-15)*5 + x -> g_B[n][k]
// proj: BM=64, BN=128, BK=64, K=640; 128 thr = 4 warps (1M x 4N).
// ---------------------------------------------------------------------------
#define PSTG 24576u
#define PROJ_SMEM (3 * 24576)

__device__ __forceinline__ void proj_load(uint32_t sbuf,
                                          const __half* __restrict__ A,
                                          const __half* __restrict__ W1T,
                                          int m0, int n0, int dof, int k0)
{
    const int tid = threadIdx.x;
    #pragma unroll
    for (int i = 0; i < 4; i++) {
        int ci = tid + i * 128;
        int row = ci >> 3;
        int ck = ci & 7;
        uint32_t so = sbuf + row * 128 + ((ck ^ (row & 7)) << 4);
        CP_ASYNC16(so, A + (size_t)(m0 + row) * DE + k0 + ck * 8);
    }
    #pragma unroll
    for (int i = 0; i < 8; i++) {
        int ci = tid + i * 128;
        int row = ci >> 3;
        int ck = ci & 7;
        uint32_t so = sbuf + 8192u + row * 128 + ((ck ^ (row & 7)) << 4);
        CP_ASYNC16(so, W1T + (size_t)(n0 + row) * DTOT + dof + k0 + ck * 8);
    }
}

__global__ void __launch_bounds__(128, 2)
proj_gemm(const __half* __restrict__ Ae,
          const __half* __restrict__ Ad,
          const __half* __restrict__ W1T,
          const float* __restrict__ b1,
          const float* __restrict__ W2,
          float* __restrict__ pe,
          float* __restrict__ pd,
          __half* __restrict__ Bt)
{
    extern __shared__ __align__(1024) char smem[];
    const int tid = threadIdx.x;

    if (blockIdx.y >= 15) {
        // ---- W2 transpose tile: Bt[n][k] = fp16(W2[k][n]), 64x64 ----
        float (*tile)[65] = reinterpret_cast<float(*)[65]>(smem);
        const int tt = (blockIdx.y - 15) * 5 + blockIdx.x;   // 0..159
        const int n0 = (tt & 15) * 64;
        const int k0 = (tt >> 4) * 64;
        const int x  = tid & 63;
        const int yq = tid >> 6;          // 0..1
        #pragma unroll
        for (int j = 0; j < 32; j++) {
            int r = yq + j * 2;
            tile[r][x] = W2[(size_t)(k0 + r) * VV + n0 + x];
        }
        __syncthreads();
        #pragma unroll
        for (int j = 0; j < 32; j++) {
            int ny = yq + j * 2;
            Bt[(size_t)(n0 + ny) * HH + k0 + x] = __float2half_rn(tile[x][ny]);
        }
        return;
    }

    // ---- projection GEMM path ----
    const uint32_t sb = smem_u32(smem);
    const int lane = tid & 31;
    const int wn   = tid >> 5;
    const int n0   = blockIdx.x * 128;
    const bool is_dec = (blockIdx.y >= 10);
    const int m0   = (is_dec ? (blockIdx.y - 10) : blockIdx.y) * 64;
    const int dof  = is_dec ? DE : 0;

    const __half* __restrict__ A = is_dec ? Ad : Ae;
    float* __restrict__ C        = is_dec ? pd : pe;

    const int lml = lane & 15;
    const int lmh = lane >> 4;

    float acc[4][4][4];
    #pragma unroll
    for (int a = 0; a < 4; a++)
        #pragma unroll
        for (int n = 0; n < 4; n++)
            #pragma unroll
            for (int i = 0; i < 4; i++) acc[a][n][i] = 0.0f;

    proj_load(sb,        A, W1T, m0, n0, dof, 0);
    CP_COMMIT();
    proj_load(sb + PSTG, A, W1T, m0, n0, dof, BK);
    CP_COMMIT();
    CP_WAIT1();
    __syncthreads();

    for (int c = 0; c < 10; c++) {
        const uint32_t sbuf = sb + (uint32_t)(c % STAGES) * PSTG;

        if (c + 2 < 10) {
            proj_load(sb + (uint32_t)((c + 2) % STAGES) * PSTG,
                      A, W1T, m0, n0, dof, (c + 2) * BK);
            CP_COMMIT();
        }

        #pragma unroll
        for (int ks = 0; ks < 4; ks++) {
            const int ck = 2 * ks + lmh;

            uint32_t af[4][4];
            #pragma unroll
            for (int a = 0; a < 4; a++) {
                uint32_t row = (uint32_t)(a * 16 + lml);
                LDSM4(af[a][0], af[a][1], af[a][2], af[a][3],
                      sbuf + row * 128 + (uint32_t)((ck ^ (row & 7)) << 4));
            }
            uint32_t bf[2][4];
            #pragma unroll
            for (int p = 0; p < 2; p++) {
                uint32_t row = (uint32_t)(wn * 32 + p * 16 + lml);
                LDSM4(bf[p][0], bf[p][1], bf[p][2], bf[p][3],
                      sbuf + 8192u + row * 128 +
                      (uint32_t)((ck ^ (row & 7)) << 4));
            }
            #pragma unroll
            for (int a = 0; a < 4; a++)
                #pragma unroll
                for (int n = 0; n < 4; n++) {
                    int p = n >> 1, s = n & 1;
                    MMA16816(acc[a][n], af[a], bf[p][s], bf[p][s + 2]);
                }
        }

        if (c + 2 < 10) CP_WAIT1();
        else            CP_WAIT0();
        __syncthreads();
    }

    #pragma unroll
    for (int n = 0; n < 4; n++) {
        const int col = n0 + wn * 32 + n * 8 + (lane & 3) * 2;
        float2 bb = make_float2(0.0f, 0.0f);
        if (is_dec) bb = *(const float2*)&b1[col];
        #pragma unroll
        for (int a = 0; a < 4; a++) {
            const int r0 = m0 + a * 16 + (lane >> 2);
            float2 o0 = { acc[a][n][0] + bb.x, acc[a][n][1] + bb.y };
            float2 o1 = { acc[a][n][2] + bb.x, acc[a][n][3] + bb.y };
            *(float2*)&C[(size_t)r0 * HH + col]       = o0;
            *(float2*)&C[(size_t)(r0 + 8) * HH + col] = o1;
        }
    }
}

// ---------------------------------------------------------------------------
// Stage 1.5: tiled A-prep. A = fp16(tanh(pe + pd)). grid (U/16, T/16, B*5).
// ---------------------------------------------------------------------------
__global__ void __launch_bounds__(256)
prep_a(__half* __restrict__ A)
{
    __shared__ float4 pe4[16][33];
    __shared__ float4 pd4[16][33];

    const int u0 = blockIdx.x * 16;
    const int t0 = blockIdx.y * 16;
    const int b  = blockIdx.z / 5;
    const int h0 = (blockIdx.z - b * 5) * 128;

    const int tid = threadIdx.x;

    {
        const int r  = tid >> 4;
        const int c4 = tid & 15;
        const float4* pe_g = (const float4*)&g_pe[(size_t)(b * T_ + t0 + r) * HH + h0];
        const float4* pd_g = (const float4*)&g_pd[(size_t)(b * U_ + u0 + r) * HH + h0];
        pe4[r][c4]      = pe_g[c4];
        pe4[r][c4 + 16] = pe_g[c4 + 16];
        pd4[r][c4]      = pd_g[c4];
        pd4[r][c4 + 16] = pd_g[c4 + 16];
    }
    __syncthreads();

    const int u_l = tid >> 4;
    const int seg = tid & 15;

    const float4 d0 = pd4[u_l][seg * 2];
    const float4 d1 = pd4[u_l][seg * 2 + 1];

    #pragma unroll
    for (int t_l = 0; t_l < 16; t_l++) {
        const float4 e0 = pe4[t_l][seg * 2];
        const float4 e1 = pe4[t_l][seg * 2 + 1];

        __half h[8];
        h[0] = __float2half_rn(fast_tanh(e0.x + d0.x));
        h[1] = __float2half_rn(fast_tanh(e0.y + d0.y));
        h[2] = __float2half_rn(fast_tanh(e0.z + d0.z));
        h[3] = __float2half_rn(fast_tanh(e0.w + d0.w));
        h[4] = __float2half_rn(fast_tanh(e1.x + d1.x));
        h[5] = __float2half_rn(fast_tanh(e1.y + d1.y));
        h[6] = __float2half_rn(fast_tanh(e1.z + d1.z));
        h[7] = __float2half_rn(fast_tanh(e1.w + d1.w));

        const size_t row = (size_t)b * TU + (t0 + t_l) * U_ + u0 + u_l;
        *(uint4*)&A[row * HH + h0 + seg * 8] = *(uint4*)h;
    }
}

// ---------------------------------------------------------------------------
// Stage 2: HMMA joint GEMM (best measured variant — unchanged).
// ---------------------------------------------------------------------------
#define STG_STRIDE 32768u
#define SMEM_TOTAL (STAGES * 32768)

__device__ __forceinline__ void load_buf(uint32_t sbuf,
                                         const __half* __restrict__ A,
                                         const __half* __restrict__ B,
                                         int m0, int n0, int k0)
{
    const int tid = threadIdx.x;
    #pragma unroll
    for (int i = 0; i < 8; i++) {
        int ci = tid + i * 128;
        int row = ci >> 3;
        int ck = ci & 7;
        uint32_t so = sbuf + row * 128 + ((ck ^ (row & 7)) << 4);
        CP_ASYNC16(so, A + (size_t)(m0 + row) * HH + k0 + ck * 8);
    }
    #pragma unroll
    for (int i = 0; i < 8; i++) {
        int ci = tid + i * 128;
        int row = ci >> 3;
        int ck = ci & 7;
        uint32_t so = sbuf + 16384u + row * 128 + ((ck ^ (row & 7)) << 4);
        CP_ASYNC16(so, B + (size_t)(n0 + row) * HH + k0 + ck * 8);
    }
}

__global__ void __launch_bounds__(128, 2)
joint_gemm(const __half* __restrict__ A,
           const __half* __restrict__ B,
           const float* __restrict__ b2,
           float* __restrict__ out)
{
    extern __shared__ __align__(1024) char smem[];
    const uint32_t sb = smem_u32(smem);

    const int tid  = threadIdx.x;
    const int lane = tid & 31;
    const int wid  = tid >> 5;
    const int wm   = wid & 1;
    const int wn   = wid >> 1;
    const int n0   = blockIdx.x * BN;
    const int m0   = blockIdx.y * BM;

    const int lml = lane & 15;
    const int lmh = lane >> 4;

    float acc[4][8][4];
    #pragma unroll
    for (int a = 0; a < 4; a++)
        #pragma unroll
        for (int n = 0; n < 8; n++)
            #pragma unroll
            for (int i = 0; i < 4; i++) acc[a][n][i] = 0.0f;

    load_buf(sb,              A, B, m0, n0, 0);
    CP_COMMIT();
    load_buf(sb + STG_STRIDE, A, B, m0, n0, BK);
    CP_COMMIT();
    CP_WAIT1();
    __syncthreads();

    for (int c = 0; c < KITERS; c++) {
        const uint32_t sbuf = sb + (uint32_t)(c % STAGES) * STG_STRIDE;

        if (c + 2 < KITERS) {
            load_buf(sb + (uint32_t)((c + 2) % STAGES) * STG_STRIDE,
                     A, B, m0, n0, (c + 2) * BK);
            CP_COMMIT();
        }

        #pragma unroll
        for (int ks = 0; ks < 4; ks++) {
            const int ck = 2 * ks + lmh;

            uint32_t af[4][4];
            #pragma unroll
            for (int a = 0; a < 4; a++) {
                uint32_t row = (uint32_t)(wm * 64 + a * 16 + lml);
                LDSM4(af[a][0], af[a][1], af[a][2], af[a][3],
                      sbuf + row * 128 + (uint32_t)((ck ^ (row & 7)) << 4));
            }
            uint32_t bf[4][4];
            #pragma unroll
            for (int p = 0; p < 4; p++) {
                uint32_t row = (uint32_t)(wn * 64 + p * 16 + lml);
                LDSM4(bf[p][0], bf[p][1], bf[p][2], bf[p][3],
                      sbuf + 16384u + row * 128 +
                      (uint32_t)((ck ^ (row & 7)) << 4));
            }
            #pragma unroll
            for (int a = 0; a < 4; a++)
                #pragma unroll
                for (int n = 0; n < 8; n++) {
                    int p = n >> 1, s = n & 1;
                    MMA16816(acc[a][n], af[a], bf[p][s], bf[p][s + 2]);
                }
        }

        if (c + 2 < KITERS) CP_WAIT1();
        else                CP_WAIT0();
        __syncthreads();
    }

    #pragma unroll
    for (int n = 0; n < 8; n++) {
        const int col = n0 + wn * 64 + n * 8 + (lane & 3) * 2;
        const float2 bb = *(const float2*)&b2[col];
        #pragma unroll
        for (int a = 0; a < 4; a++) {
            const size_t r0 = (size_t)m0 + wm * 64 + a * 16 + (lane >> 2);
            float2 o0 = { acc[a][n][0] + bb.x, acc[a][n][1] + bb.y };
            float2 o1 = { acc[a][n][2] + bb.x, acc[a][n][3] + bb.y };
            *(float2*)&out[r0 * VV + col]       = o0;
            *(float2*)&out[(r0 + 8) * VV + col] = o1;
        }
    }
}

// ---------------------------------------------------------------------------
// Launch: 4 kernels (W2T overlapped under proj_gemm)
// ---------------------------------------------------------------------------
extern "C" void kernel_launch(void* const* d_in, const int* in_sizes, int n_in,
                              void* d_out, int out_size)
{
    const float* enc = (const float*)d_in[0];
    const float* dec = (const float*)d_in[1];
    const float* W1  = (const float*)d_in[2];
    const float* b1  = (const float*)d_in[3];
    const float* W2  = (const float*)d_in[4];
    const float* b2  = (const float*)d_in[5];
    float* out = (float*)d_out;

    float *pe = nullptr, *pd = nullptr;
    __half *ga = nullptr, *gb = nullptr, *gae = nullptr, *gad = nullptr,
           *gw1t = nullptr;
    cudaGetSymbolAddress((void**)&pe,   g_pe);
    cudaGetSymbolAddress((void**)&pd,   g_pd);
    cudaGetSymbolAddress((void**)&ga,   g_A);
    cudaGetSymbolAddress((void**)&gb,   g_B);
    cudaGetSymbolAddress((void**)&gae,  g_Ae);
    cudaGetSymbolAddress((void**)&gad,  g_Ad);
    cudaGetSymbolAddress((void**)&gw1t, g_W1T);

    cudaFuncSetAttribute(joint_gemm,
                         cudaFuncAttributeMaxDynamicSharedMemorySize, SMEM_TOTAL);
    cudaFuncSetAttribute(proj_gemm,
                         cudaFuncAttributeMaxDynamicSharedMemorySize, PROJ_SMEM);

    // W1 transpose + fp16 conversions
    prep_static<<<350, 256>>>(enc, dec, W1, gae, gad, gw1t);
    // tensor-core projections (+b1 on dec) with W2 transpose overlapped
    proj_gemm<<<dim3(HH / 128, 47), 128, PROJ_SMEM>>>(gae, gad, gw1t, b1, W2,
                                                      pe, pd, gb);
    // tiled tanh + fp16 pack
    prep_a<<<dim3(U_ / 16, T_ / 16, B_ * 5), 256>>>(ga);
    // joint GEMM
    joint_gemm<<<dim3(VV / BN, MTOT / BM), 128, SMEM_TOTAL>>>(ga, gb, b2, out);
}

// round 13
// speedup vs baseline: 1.2918x; 1.0497x over previous
#include <cuda_runtime.h>
#include <cuda_fp16.h>
#include <cstdint>

// ---------------------------------------------------------------------------
// Problem constants
// ---------------------------------------------------------------------------
#define B_ 4
#define T_ 160
#define U_ 80
#define DE 640
#define DTOT 1280
#define HH 640
#define VV 1024
#define TU (T_ * U_)          // 12800
#define MTOT (B_ * TU)        // 51200

// Joint GEMM tiling
#define BM 128
#define BN 128
#define BK 64
#define KITERS (HH / BK)      // 10
#define STAGES 3

// ---------------------------------------------------------------------------
// Device scratch
// ---------------------------------------------------------------------------
__device__ float g_pe[B_ * T_ * HH];
__device__ float g_pd[B_ * U_ * HH];
__device__ __align__(16) __half g_Ae[B_ * T_ * DE];       // fp16(enc)
__device__ __align__(16) __half g_Ad[B_ * U_ * DE];       // fp16(dec)
__device__ __align__(16) __half g_W1T[HH * DTOT];         // W1^T [h][d]
__device__ __align__(16) __half g_A[(size_t)MTOT * HH];   // fp16(tanh(...))
__device__ __align__(16) __half g_B[VV * HH];             // W2^T fp16 [n][k]

// ---------------------------------------------------------------------------
// Helpers
// ---------------------------------------------------------------------------
__device__ __forceinline__ uint32_t smem_u32(const void* p) {
    uint32_t a;
    asm("{ .reg .u64 t; cvta.to.shared.u64 t, %1; cvt.u32.u64 %0, t; }"
        : "=r"(a) : "l"(p));
    return a;
}

__device__ __forceinline__ float fast_tanh(float x) {
    float e;
    asm("ex2.approx.f32 %0, %1;" : "=f"(e) : "f"(x * 2.885390081777927f));
    float r;
    asm("rcp.approx.f32 %0, %1;" : "=f"(r) : "f"(e + 1.0f));
    return fmaf(-2.0f, r, 1.0f);
}

#define CP_ASYNC16(saddr, gptr) \
    asm volatile("cp.async.cg.shared.global [%0], [%1], 16;" \
                 :: "r"(saddr), "l"(gptr))
#define CP_COMMIT()  asm volatile("cp.async.commit_group;" ::: "memory")
#define CP_WAIT1()   asm volatile("cp.async.wait_group 1;" ::: "memory")
#define CP_WAIT0()   asm volatile("cp.async.wait_group 0;" ::: "memory")

#define LDSM4(r0, r1, r2, r3, a) \
    asm volatile("ldmatrix.sync.aligned.m8n8.x4.shared.b16 {%0,%1,%2,%3}, [%4];" \
                 : "=r"(r0), "=r"(r1), "=r"(r2), "=r"(r3) : "r"(a))

#define MMA16816(d, a, b0, b1) \
    asm volatile("mma.sync.aligned.m16n8k16.row.col.f32.f16.f16.f32 " \
                 "{%0,%1,%2,%3}, {%4,%5,%6,%7}, {%8,%9}, {%0,%1,%2,%3};" \
                 : "+f"((d)[0]), "+f"((d)[1]), "+f"((d)[2]), "+f"((d)[3]) \
                 : "r"((a)[0]), "r"((a)[1]), "r"((a)[2]), "r"((a)[3]), \
                   "r"(b0), "r"(b1))

// ---------------------------------------------------------------------------
// Stage 0: prep_static — W1 transpose + enc/dec fp16 conversion. 350 CTAs.
// ---------------------------------------------------------------------------
__global__ void __launch_bounds__(256)
prep_static(const float* __restrict__ enc,
            const float* __restrict__ dec,
            const float* __restrict__ W1,
            __half* __restrict__ Ae,
            __half* __restrict__ Ad,
            __half* __restrict__ W1T)
{
    const int tid = threadIdx.x;
    const int bx  = blockIdx.x;

    if (bx < 200) {                       // W1: [1280,640] -> g_W1T[h][d]
        __shared__ float tile[64][65];
        const int h0 = (bx % 10) * 64;
        const int d0 = (bx / 10) * 64;
        const int x  = tid & 63;
        const int yq = tid >> 6;
        #pragma unroll
        for (int j = 0; j < 16; j++) {
            int r = yq + j * 4;
            tile[r][x] = W1[(size_t)(d0 + r) * HH + h0 + x];
        }
        __syncthreads();
        #pragma unroll
        for (int j = 0; j < 16; j++) {
            int ny = yq + j * 4;
            W1T[(size_t)(h0 + ny) * DTOT + d0 + x] =
                __float2half_rn(tile[x][ny]);
        }
        return;
    }

    const int cb = bx - 200;
    const float* __restrict__ src;
    __half* __restrict__ dst;
    size_t off;
    if (cb < 100) { src = enc; dst = Ae; off = (size_t)cb * 4096; }
    else          { src = dec; dst = Ad; off = (size_t)(cb - 100) * 4096; }

    #pragma unroll
    for (int i = 0; i < 4; i++) {
        const size_t idx = off + (size_t)i * 1024 + tid * 4;
        float4 v = *(const float4*)&src[idx];
        __half h[4];
        h[0] = __float2half_rn(v.x);
        h[1] = __float2half_rn(v.y);
        h[2] = __float2half_rn(v.z);
        h[3] = __float2half_rn(v.w);
        *(uint2*)&dst[idx] = *(uint2*)h;
    }
}

// ---------------------------------------------------------------------------
// Stage 1: HMMA projection GEMM + W2 transpose (overlapped in one grid).
// ---------------------------------------------------------------------------
#define PSTG 24576u
#define PROJ_SMEM (3 * 24576)

__device__ __forceinline__ void proj_load(uint32_t sbuf,
                                          const __half* __restrict__ aB,
                                          const __half* __restrict__ bB,
                                          int k0)
{
    const int tid = threadIdx.x;
    #pragma unroll
    for (int i = 0; i < 4; i++) {
        int ci = tid + i * 128;
        int row = ci >> 3;
        int ck = ci & 7;
        uint32_t so = sbuf + row * 128 + ((ck ^ (row & 7)) << 4);
        CP_ASYNC16(so, aB + (size_t)row * DE + k0 + ck * 8);
    }
    #pragma unroll
    for (int i = 0; i < 8; i++) {
        int ci = tid + i * 128;
        int row = ci >> 3;
        int ck = ci & 7;
        uint32_t so = sbuf + 8192u + row * 128 + ((ck ^ (row & 7)) << 4);
        CP_ASYNC16(so, bB + (size_t)row * DTOT + k0 + ck * 8);
    }
}

__global__ void __launch_bounds__(128, 2)
proj_gemm(const __half* __restrict__ Ae,
          const __half* __restrict__ Ad,
          const __half* __restrict__ W1T,
          const float* __restrict__ b1,
          const float* __restrict__ W2,
          float* __restrict__ pe,
          float* __restrict__ pd,
          __half* __restrict__ Bt)
{
    extern __shared__ __align__(1024) char smem[];
    const int tid = threadIdx.x;

    if (blockIdx.y >= 15) {
        // ---- W2 transpose tile: Bt[n][k] = fp16(W2[k][n]), 64x64 ----
        float (*tile)[65] = reinterpret_cast<float(*)[65]>(smem);
        const int tt = (blockIdx.y - 15) * 5 + blockIdx.x;
        const int n0 = (tt & 15) * 64;
        const int k0 = (tt >> 4) * 64;
        const int x  = tid & 63;
        const int yq = tid >> 6;
        #pragma unroll
        for (int j = 0; j < 32; j++) {
            int r = yq + j * 2;
            tile[r][x] = W2[(size_t)(k0 + r) * VV + n0 + x];
        }
        __syncthreads();
        #pragma unroll
        for (int j = 0; j < 32; j++) {
            int ny = yq + j * 2;
            Bt[(size_t)(n0 + ny) * HH + k0 + x] = __float2half_rn(tile[x][ny]);
        }
        return;
    }

    const uint32_t sb = smem_u32(smem);
    const int lane = tid & 31;
    const int wn   = tid >> 5;
    const int n0   = blockIdx.x * 128;
    const bool is_dec = (blockIdx.y >= 10);
    const int m0   = (is_dec ? (blockIdx.y - 10) : blockIdx.y) * 64;
    const int dof  = is_dec ? DE : 0;

    const __half* __restrict__ aB = (is_dec ? Ad : Ae) + (size_t)m0 * DE;
    const __half* __restrict__ bB = W1T + (size_t)n0 * DTOT + dof;
    float* __restrict__ C         = is_dec ? pd : pe;

    const int lml = lane & 15;
    const int lmh = lane >> 4;

    float acc[4][4][4];
    #pragma unroll
    for (int a = 0; a < 4; a++)
        #pragma unroll
        for (int n = 0; n < 4; n++)
            #pragma unroll
            for (int i = 0; i < 4; i++) acc[a][n][i] = 0.0f;

    proj_load(sb,        aB, bB, 0);
    CP_COMMIT();
    proj_load(sb + PSTG, aB, bB, BK);
    CP_COMMIT();
    CP_WAIT1();
    __syncthreads();

    #pragma unroll
    for (int c = 0; c < 10; c++) {
        const uint32_t sbuf = sb + (uint32_t)(c % STAGES) * PSTG;

        if (c + 2 < 10) {
            proj_load(sb + (uint32_t)((c + 2) % STAGES) * PSTG,
                      aB, bB, (c + 2) * BK);
            CP_COMMIT();
        }

        #pragma unroll
        for (int ks = 0; ks < 4; ks++) {
            const int ck = 2 * ks + lmh;

            uint32_t af[4][4];
            #pragma unroll
            for (int a = 0; a < 4; a++) {
                uint32_t row = (uint32_t)(a * 16 + lml);
                LDSM4(af[a][0], af[a][1], af[a][2], af[a][3],
                      sbuf + row * 128 + (uint32_t)((ck ^ (row & 7)) << 4));
            }
            uint32_t bf[2][4];
            #pragma unroll
            for (int p = 0; p < 2; p++) {
                uint32_t row = (uint32_t)(wn * 32 + p * 16 + lml);
                LDSM4(bf[p][0], bf[p][1], bf[p][2], bf[p][3],
                      sbuf + 8192u + row * 128 +
                      (uint32_t)((ck ^ (row & 7)) << 4));
            }
            #pragma unroll
            for (int a = 0; a < 4; a++)
                #pragma unroll
                for (int n = 0; n < 4; n++) {
                    int p = n >> 1, s = n & 1;
                    MMA16816(acc[a][n], af[a], bf[p][s], bf[p][s + 2]);
                }
        }

        if (c + 2 < 10) CP_WAIT1();
        else            CP_WAIT0();
        __syncthreads();
    }

    #pragma unroll
    for (int n = 0; n < 4; n++) {
        const int col = n0 + wn * 32 + n * 8 + (lane & 3) * 2;
        float2 bb = make_float2(0.0f, 0.0f);
        if (is_dec) bb = *(const float2*)&b1[col];
        #pragma unroll
        for (int a = 0; a < 4; a++) {
            const int r0 = m0 + a * 16 + (lane >> 2);
            float2 o0 = { acc[a][n][0] + bb.x, acc[a][n][1] + bb.y };
            float2 o1 = { acc[a][n][2] + bb.x, acc[a][n][3] + bb.y };
            *(float2*)&C[(size_t)r0 * HH + col]       = o0;
            *(float2*)&C[(size_t)(r0 + 8) * HH + col] = o1;
        }
    }
}

// ---------------------------------------------------------------------------
// Stage 1.5: tiled A-prep. A = fp16(tanh(pe + pd)). grid (U/16, T/16, B*5).
// ---------------------------------------------------------------------------
__global__ void __launch_bounds__(256)
prep_a(__half* __restrict__ A)
{
    __shared__ float4 pe4[16][33];
    __shared__ float4 pd4[16][33];

    const int u0 = blockIdx.x * 16;
    const int t0 = blockIdx.y * 16;
    const int b  = blockIdx.z / 5;
    const int h0 = (blockIdx.z - b * 5) * 128;

    const int tid = threadIdx.x;

    {
        const int r  = tid >> 4;
        const int c4 = tid & 15;
        const float4* pe_g = (const float4*)&g_pe[(size_t)(b * T_ + t0 + r) * HH + h0];
        const float4* pd_g = (const float4*)&g_pd[(size_t)(b * U_ + u0 + r) * HH + h0];
        pe4[r][c4]      = pe_g[c4];
        pe4[r][c4 + 16] = pe_g[c4 + 16];
        pd4[r][c4]      = pd_g[c4];
        pd4[r][c4 + 16] = pd_g[c4 + 16];
    }
    __syncthreads();

    const int u_l = tid >> 4;
    const int seg = tid & 15;

    const float4 d0 = pd4[u_l][seg * 2];
    const float4 d1 = pd4[u_l][seg * 2 + 1];

    #pragma unroll
    for (int t_l = 0; t_l < 16; t_l++) {
        const float4 e0 = pe4[t_l][seg * 2];
        const float4 e1 = pe4[t_l][seg * 2 + 1];

        __half h[8];
        h[0] = __float2half_rn(fast_tanh(e0.x + d0.x));
        h[1] = __float2half_rn(fast_tanh(e0.y + d0.y));
        h[2] = __float2half_rn(fast_tanh(e0.z + d0.z));
        h[3] = __float2half_rn(fast_tanh(e0.w + d0.w));
        h[4] = __float2half_rn(fast_tanh(e1.x + d1.x));
        h[5] = __float2half_rn(fast_tanh(e1.y + d1.y));
        h[6] = __float2half_rn(fast_tanh(e1.z + d1.z));
        h[7] = __float2half_rn(fast_tanh(e1.w + d1.w));

        const size_t row = (size_t)b * TU + (t0 + t_l) * U_ + u0 + u_l;
        *(uint4*)&A[row * HH + h0 + seg * 8] = *(uint4*)h;
    }
}

// ---------------------------------------------------------------------------
// Stage 2: HMMA joint GEMM — fully unrolled mainloop (constant-folded
// stage offsets, immediate-offset cp.async/LDSM addressing).
// BM=128, BN=128, BK=64; 128 threads = 4 warps (2M x 2N), warp tile 64x64.
// ---------------------------------------------------------------------------
#define STG_STRIDE 32768u
#define SMEM_TOTAL (STAGES * 32768)

__device__ __forceinline__ void load_buf(uint32_t sbuf,
                                         const __half* __restrict__ aB,
                                         const __half* __restrict__ bB,
                                         int k0)
{
    const int tid = threadIdx.x;
    #pragma unroll
    for (int i = 0; i < 8; i++) {
        int ci = tid + i * 128;
        int row = ci >> 3;
        int ck = ci & 7;
        uint32_t so = sbuf + row * 128 + ((ck ^ (row & 7)) << 4);
        CP_ASYNC16(so, aB + (size_t)row * HH + k0 + ck * 8);
    }
    #pragma unroll
    for (int i = 0; i < 8; i++) {
        int ci = tid + i * 128;
        int row = ci >> 3;
        int ck = ci & 7;
        uint32_t so = sbuf + 16384u + row * 128 + ((ck ^ (row & 7)) << 4);
        CP_ASYNC16(so, bB + (size_t)row * HH + k0 + ck * 8);
    }
}

__global__ void __launch_bounds__(128, 2)
joint_gemm(const __half* __restrict__ A,
           const __half* __restrict__ B,
           const float* __restrict__ b2,
           float* __restrict__ out)
{
    extern __shared__ __align__(1024) char smem[];
    const uint32_t sb = smem_u32(smem);

    const int tid  = threadIdx.x;
    const int lane = tid & 31;
    const int wid  = tid >> 5;
    const int wm   = wid & 1;
    const int wn   = wid >> 1;
    const int n0   = blockIdx.x * BN;
    const int m0   = blockIdx.y * BM;

    // hoisted block-base pointers (k advances by constant per unrolled iter)
    const __half* __restrict__ aB = A + (size_t)m0 * HH;
    const __half* __restrict__ bB = B + (size_t)n0 * HH;

    const int lml = lane & 15;
    const int lmh = lane >> 4;

    float acc[4][8][4];
    #pragma unroll
    for (int a = 0; a < 4; a++)
        #pragma unroll
        for (int n = 0; n < 8; n++)
            #pragma unroll
            for (int i = 0; i < 4; i++) acc[a][n][i] = 0.0f;

    load_buf(sb,              aB, bB, 0);
    CP_COMMIT();
    load_buf(sb + STG_STRIDE, aB, bB, BK);
    CP_COMMIT();
    CP_WAIT1();
    __syncthreads();

    #pragma unroll
    for (int c = 0; c < KITERS; c++) {
        const uint32_t sbuf = sb + (uint32_t)(c % STAGES) * STG_STRIDE;

        if (c + 2 < KITERS) {
            load_buf(sb + (uint32_t)((c + 2) % STAGES) * STG_STRIDE,
                     aB, bB, (c + 2) * BK);
            CP_COMMIT();
        }

        #pragma unroll
        for (int ks = 0; ks < 4; ks++) {
            const int ck = 2 * ks + lmh;

            uint32_t af[4][4];
            #pragma unroll
            for (int a = 0; a < 4; a++) {
                uint32_t row = (uint32_t)(wm * 64 + a * 16 + lml);
                LDSM4(af[a][0], af[a][1], af[a][2], af[a][3],
                      sbuf + row * 128 + (uint32_t)((ck ^ (row & 7)) << 4));
            }
            uint32_t bf[4][4];
            #pragma unroll
            for (int p = 0; p < 4; p++) {
                uint32_t row = (uint32_t)(wn * 64 + p * 16 + lml);
                LDSM4(bf[p][0], bf[p][1], bf[p][2], bf[p][3],
                      sbuf + 16384u + row * 128 +
                      (uint32_t)((ck ^ (row & 7)) << 4));
            }
            #pragma unroll
            for (int a = 0; a < 4; a++)
                #pragma unroll
                for (int n = 0; n < 8; n++) {
                    int p = n >> 1, s = n & 1;
                    MMA16816(acc[a][n], af[a], bf[p][s], bf[p][s + 2]);
                }
        }

        if (c + 2 < KITERS) CP_WAIT1();
        else                CP_WAIT0();
        __syncthreads();
    }

    #pragma unroll
    for (int n = 0; n < 8; n++) {
        const int col = n0 + wn * 64 + n * 8 + (lane & 3) * 2;
        const float2 bb = *(const float2*)&b2[col];
        #pragma unroll
        for (int a = 0; a < 4; a++) {
            const size_t r0 = (size_t)m0 + wm * 64 + a * 16 + (lane >> 2);
            float2 o0 = { acc[a][n][0] + bb.x, acc[a][n][1] + bb.y };
            float2 o1 = { acc[a][n][2] + bb.x, acc[a][n][3] + bb.y };
            *(float2*)&out[r0 * VV + col]       = o0;
            *(float2*)&out[(r0 + 8) * VV + col] = o1;
        }
    }
}

// ---------------------------------------------------------------------------
// Launch: 4 kernels
// ---------------------------------------------------------------------------
extern "C" void kernel_launch(void* const* d_in, const int* in_sizes, int n_in,
                              void* d_out, int out_size)
{
    const float* enc = (const float*)d_in[0];
    const float* dec = (const float*)d_in[1];
    const float* W1  = (const float*)d_in[2];
    const float* b1  = (const float*)d_in[3];
    const float* W2  = (const float*)d_in[4];
    const float* b2  = (const float*)d_in[5];
    float* out = (float*)d_out;

    float *pe = nullptr, *pd = nullptr;
    __half *ga = nullptr, *gb = nullptr, *gae = nullptr, *gad = nullptr,
           *gw1t = nullptr;
    cudaGetSymbolAddress((void**)&pe,   g_pe);
    cudaGetSymbolAddress((void**)&pd,   g_pd);
    cudaGetSymbolAddress((void**)&ga,   g_A);
    cudaGetSymbolAddress((void**)&gb,   g_B);
    cudaGetSymbolAddress((void**)&gae,  g_Ae);
    cudaGetSymbolAddress((void**)&gad,  g_Ad);
    cudaGetSymbolAddress((void**)&gw1t, g_W1T);

    cudaFuncSetAttribute(joint_gemm,
                         cudaFuncAttributeMaxDynamicSharedMemorySize, SMEM_TOTAL);
    cudaFuncSetAttribute(proj_gemm,
                         cudaFuncAttributeMaxDynamicSharedMemorySize, PROJ_SMEM);

    prep_static<<<350, 256>>>(enc, dec, W1, gae, gad, gw1t);
    proj_gemm<<<dim3(HH / 128, 47), 128, PROJ_SMEM>>>(gae, gad, gw1t, b1, W2,
                                                      pe, pd, gb);
    prep_a<<<dim3(U_ / 16, T_ / 16, B_ * 5), 256>>>(ga);
    joint_gemm<<<dim3(VV / BN, MTOT / BM), 128, SMEM_TOTAL>>>(ga, gb, b2, out);
}